// round 5
// baseline (speedup 1.0000x reference)
#include <cuda_runtime.h>

// ---------------- problem constants ----------------
#define BB 16
#define TT 4096
#define CIN 80
#define H1C 128
#define H2C 256
#define DDIM 64
#define KCODES 512

#define REC_ELEMS (BB*CIN*TT)   // 5242880
#define IDX_ELEMS (BB*TT)       // 65536

// ---------------- device scratch (no allocs allowed) ----------------
__device__ float g_buf1[BB*H2C*TT];
__device__ float g_buf2[BB*H2C*TT];
__device__ float g_z  [BB*DDIM*TT];
__device__ float g_q  [BB*DDIM*TT];
__device__ float g_mean[H2C];
__device__ float g_rstd[H2C];
__device__ float g_cnorm[KCODES];
__device__ float g_loss;

// ============================================================
// conv1d, Eigen-faithful: per output a single sequential fma chain over
// k = (kw outer, ci inner ascending); zero-pads are exact fma no-ops;
// bias added afterwards as one fadd.
// ============================================================
template<int K>
__global__ __launch_bounds__(256, 2)
void conv_exact(const float* __restrict__ in, const float* __restrict__ w,
                const float* __restrict__ bias, float* __restrict__ out,
                int Ci, int Co)
{
    const int pad = K / 2;
    __shared__ float xs[16][256];
    __shared__ float ws[64][16];

    const int tid = threadIdx.x;
    const int tx = tid & 31;
    const int ty = tid >> 5;
    const int t0  = blockIdx.x * 256;
    const int co0 = blockIdx.y * 64;
    const int b   = blockIdx.z;

    float acc[8][8];
    #pragma unroll
    for (int i = 0; i < 8; i++)
        #pragma unroll
        for (int j = 0; j < 8; j++) acc[i][j] = 0.f;

    const int nchunks = Ci / 16;
    #pragma unroll
    for (int kw = 0; kw < K; kw++) {
        for (int cic = 0; cic < nchunks; ++cic) {
            const int ci0 = cic * 16;
            __syncthreads();
            #pragma unroll
            for (int it = 0; it < 16; it++) {
                int idx = tid + it * 256;
                int r = idx >> 8, col = idx & 255;
                int gt = t0 + col + kw - pad;
                float v = 0.f;
                if (gt >= 0 && gt < TT)
                    v = in[((size_t)(b * Ci + ci0 + r)) * TT + gt];
                xs[r][col] = v;
            }
            {
                int idx = tid;
                #pragma unroll
                for (int it = 0; it < 4; it++, idx += 256) {
                    int cl = idx >> 4, cc = idx & 15;
                    int co = co0 + cl;
                    ws[cl][cc] = (co < Co) ? w[((size_t)co * Ci + ci0 + cc) * K + kw] : 0.f;
                }
            }
            __syncthreads();

            #pragma unroll
            for (int cc = 0; cc < 16; ++cc) {
                float xr[8];
                #pragma unroll
                for (int j = 0; j < 8; j++) xr[j] = xs[cc][tx + 32 * j];
                #pragma unroll
                for (int i = 0; i < 8; i++) {
                    float wv = ws[ty + 8 * i][cc];
                    #pragma unroll
                    for (int j = 0; j < 8; j++)
                        acc[i][j] = __fmaf_rn(xr[j], wv, acc[i][j]);
                }
            }
        }
    }

    #pragma unroll
    for (int i = 0; i < 8; i++) {
        int co = co0 + ty + 8 * i;
        if (co < Co) {
            float bv = bias[co];
            float* op = out + ((size_t)(b * Co + co)) * TT + t0;
            #pragma unroll
            for (int j = 0; j < 8; j++)
                op[tx + 32 * j] = __fadd_rn(acc[i][j], bv);
        }
    }
}

// ============================================================
// BN stats, TWO-LEVEL chain hypothesis (reduce{t} then reduce{n}):
//   s_n = sequential sum over t (4096 fadds);  S = sequential sum of s_n (n ascending)
//   v_n = sequential sum over t of (x-m)^2 (mul-then-add);  V = sum of v_n
//   mean = S/65536 ; var = V/65536 ; rstd = 1/sqrt(var+eps)
// One thread per channel.
// ============================================================
__global__ __launch_bounds__(32)
void bnstats_exact(const float* __restrict__ x, int C)
{
    const int c = blockIdx.x * 32 + threadIdx.x;
    if (c >= C) return;

    // ---- pass 1: mean, per-batch subtotals then sum over n ----
    float S = 0.f;
    for (int b = 0; b < BB; b++) {
        const float* p = x + ((size_t)(b * C + c)) * TT;
        float s = 0.f;
        for (int t = 0; t < TT; t += 8) {
            float4 a0 = __ldg((const float4*)(p + t));
            float4 a1 = __ldg((const float4*)(p + t + 4));
            s = __fadd_rn(s, a0.x); s = __fadd_rn(s, a0.y);
            s = __fadd_rn(s, a0.z); s = __fadd_rn(s, a0.w);
            s = __fadd_rn(s, a1.x); s = __fadd_rn(s, a1.y);
            s = __fadd_rn(s, a1.z); s = __fadd_rn(s, a1.w);
        }
        S = __fadd_rn(S, s);
    }
    const float m = __fdiv_rn(S, (float)(BB * TT));

    // ---- pass 2: var, same two-level structure, mul-then-add ----
    float V = 0.f;
    for (int b = 0; b < BB; b++) {
        const float* p = x + ((size_t)(b * C + c)) * TT;
        float s2 = 0.f;
        for (int t = 0; t < TT; t += 8) {
            float4 a0 = __ldg((const float4*)(p + t));
            float4 a1 = __ldg((const float4*)(p + t + 4));
            float d;
            d = __fsub_rn(a0.x, m); s2 = __fadd_rn(s2, __fmul_rn(d, d));
            d = __fsub_rn(a0.y, m); s2 = __fadd_rn(s2, __fmul_rn(d, d));
            d = __fsub_rn(a0.z, m); s2 = __fadd_rn(s2, __fmul_rn(d, d));
            d = __fsub_rn(a0.w, m); s2 = __fadd_rn(s2, __fmul_rn(d, d));
            d = __fsub_rn(a1.x, m); s2 = __fadd_rn(s2, __fmul_rn(d, d));
            d = __fsub_rn(a1.y, m); s2 = __fadd_rn(s2, __fmul_rn(d, d));
            d = __fsub_rn(a1.z, m); s2 = __fadd_rn(s2, __fmul_rn(d, d));
            d = __fsub_rn(a1.w, m); s2 = __fadd_rn(s2, __fmul_rn(d, d));
        }
        V = __fadd_rn(V, s2);
    }
    const float var = __fdiv_rn(V, (float)(BB * TT));
    g_mean[c] = m;
    g_rstd[c] = __fdiv_rn(1.0f, __fsqrt_rn(__fadd_rn(var, 1e-5f)));
}

// ---------------- fast parallel BN stats (decoder, 1e-3 path) ----------------
__global__ void bnstats_fast(const float* __restrict__ x, int C)
{
    const int c = blockIdx.x;
    float s = 0.f, s2 = 0.f;
    for (int b = 0; b < BB; b++) {
        const float* p = x + (size_t)(b * C + c) * TT;
        for (int t = threadIdx.x; t < TT; t += 256) {
            float v = p[t];
            s += v; s2 += v * v;
        }
    }
    #pragma unroll
    for (int o = 16; o > 0; o >>= 1) {
        s  += __shfl_down_sync(0xffffffffu, s,  o);
        s2 += __shfl_down_sync(0xffffffffu, s2, o);
    }
    __shared__ float sa[8], sb[8];
    int wrp = threadIdx.x >> 5, ln = threadIdx.x & 31;
    if (ln == 0) { sa[wrp] = s; sb[wrp] = s2; }
    __syncthreads();
    if (threadIdx.x == 0) {
        float ts = 0.f, ts2 = 0.f;
        #pragma unroll
        for (int i = 0; i < 8; i++) { ts += sa[i]; ts2 += sb[i]; }
        const float invn = 1.f / (float)(BB * TT);
        float m = ts * invn;
        float var = ts2 * invn - m * m;
        g_mean[c] = m;
        g_rstd[c] = __fdiv_rn(1.0f, __fsqrt_rn(__fadd_rn(var, 1e-5f)));
    }
}

// ---------------- BN apply + relu: ((x-m)*r)*g + b ----------------
__global__ void bnrelu_exact(float* __restrict__ x, const float* __restrict__ gam,
                             const float* __restrict__ bet, int Cmask, int n)
{
    int i = blockIdx.x * 256 + threadIdx.x;
    if (i >= n) return;
    int c = (i >> 12) & Cmask;
    float v = __fadd_rn(
        __fmul_rn(__fmul_rn(__fsub_rn(x[i], g_mean[c]), g_rstd[c]), gam[c]),
        bet[c]);
    x[i] = v > 0.f ? v : 0.f;
}

// ---------------- VQ ----------------
__global__ void zero_loss_kernel() { g_loss = 0.f; }

__global__ void cnorm_exact(const float* __restrict__ cb)
{
    int c = blockIdx.x * 256 + threadIdx.x;
    if (c >= KCODES) return;
    float s = 0.f;
    #pragma unroll
    for (int d = 0; d < DDIM; d++) {
        float v = cb[c * DDIM + d];
        s = __fadd_rn(s, __fmul_rn(v, v));
    }
    g_cnorm[c] = s;
}

// d2 = fl( fl(S1 + cn) - fl(2*dot) ), dot sequential fma d=0..63,
// argmin strict < (first index wins). Writes q_st = fl(z + fl(q - z)).
__global__ __launch_bounds__(128)
void vq_exact(const float* __restrict__ z, const float* __restrict__ cb,
              float* __restrict__ q, float* __restrict__ idx_out)
{
    __shared__ __align__(16) float cs[128 * DDIM];
    __shared__ float cn[128];
    __shared__ float red[4];

    const int tid = threadIdx.x;
    const int n = blockIdx.x * 128 + tid;
    const int b = n >> 12;
    const int t = n & (TT - 1);

    float zv[DDIM];
    #pragma unroll
    for (int d = 0; d < DDIM; d++) zv[d] = z[(size_t)(b * DDIM + d) * TT + t];

    float s1 = 0.f;
    #pragma unroll
    for (int d = 0; d < DDIM; d++) s1 = __fadd_rn(s1, __fmul_rn(zv[d], zv[d]));

    float best = 3.402823466e38f;
    int bidx = 0;

    for (int ch = 0; ch < KCODES / 128; ++ch) {
        __syncthreads();
        for (int i = tid; i < 128 * DDIM; i += 128)
            cs[i] = cb[ch * 128 * DDIM + i];
        cn[tid] = g_cnorm[ch * 128 + tid];
        __syncthreads();

        #pragma unroll 4
        for (int c = 0; c < 128; ++c) {
            const float* cv = &cs[c * DDIM];
            float dot = 0.f;
            #pragma unroll
            for (int d = 0; d < DDIM; d++)
                dot = __fmaf_rn(zv[d], cv[d], dot);
            float a  = __fadd_rn(s1, cn[c]);
            float d2 = __fsub_rn(a, __fmul_rn(2.0f, dot));
            if (d2 < best) { best = d2; bidx = ch * 128 + c; }
        }
    }

    idx_out[n] = (float)bidx;

    float lsum = 0.f;
    #pragma unroll
    for (int d = 0; d < DDIM; d++) {
        float cv = cb[bidx * DDIM + d];
        // straight-through value as the reference computes it:
        // q_st = fl( z + fl(q - z) )  (NOT exactly q)
        float qst = __fadd_rn(zv[d], __fsub_rn(cv, zv[d]));
        q[(size_t)(b * DDIM + d) * TT + t] = qst;
        float df = cv - zv[d];
        lsum += df * df;
    }
    #pragma unroll
    for (int o = 16; o > 0; o >>= 1)
        lsum += __shfl_down_sync(0xffffffffu, lsum, o);
    if ((tid & 31) == 0) red[tid >> 5] = lsum;
    __syncthreads();
    if (tid == 0)
        atomicAdd(&g_loss, red[0] + red[1] + red[2] + red[3]);
}

__global__ void finalize_kernel(float* __restrict__ out)
{
    out[REC_ELEMS] = 1.25f * g_loss / (float)(BB * TT * DDIM);
}

// ---------------- launch ----------------
extern "C" void kernel_launch(void* const* d_in, const int* in_sizes, int n_in,
                              void* d_out, int out_size)
{
    const float* x      = (const float*)d_in[0];
    const float* enc_w1 = (const float*)d_in[1];
    const float* enc_b1 = (const float*)d_in[2];
    const float* bn1_g  = (const float*)d_in[3];
    const float* bn1_b  = (const float*)d_in[4];
    const float* enc_w2 = (const float*)d_in[5];
    const float* enc_b2 = (const float*)d_in[6];
    const float* bn2_g  = (const float*)d_in[7];
    const float* bn2_b  = (const float*)d_in[8];
    const float* enc_w3 = (const float*)d_in[9];
    const float* enc_b3 = (const float*)d_in[10];
    const float* cb     = (const float*)d_in[11];
    const float* dec_w1 = (const float*)d_in[12];
    const float* dec_b1 = (const float*)d_in[13];
    const float* dbn1_g = (const float*)d_in[14];
    const float* dbn1_b = (const float*)d_in[15];
    const float* dec_w2 = (const float*)d_in[16];
    const float* dec_b2 = (const float*)d_in[17];
    const float* dbn2_g = (const float*)d_in[18];
    const float* dbn2_b = (const float*)d_in[19];
    const float* dec_w3 = (const float*)d_in[20];
    const float* dec_b3 = (const float*)d_in[21];

    float* out = (float*)d_out;
    float* idx_out = out + REC_ELEMS + 1;

    float *buf1, *buf2, *zb, *qb;
    cudaGetSymbolAddress((void**)&buf1, g_buf1);
    cudaGetSymbolAddress((void**)&buf2, g_buf2);
    cudaGetSymbolAddress((void**)&zb,   g_z);
    cudaGetSymbolAddress((void**)&qb,   g_q);

    const dim3 blk(256);
    const int tg = TT / 256;   // 16

    // ---- encoder (bitwise path) ----
    conv_exact<3><<<dim3(tg, H1C / 64, BB), blk>>>(x, enc_w1, enc_b1, buf1, CIN, H1C);
    bnstats_exact<<<H1C / 32, 32>>>(buf1, H1C);
    bnrelu_exact<<<(BB * H1C * TT) / 256, 256>>>(buf1, bn1_g, bn1_b, H1C - 1, BB * H1C * TT);

    conv_exact<3><<<dim3(tg, H2C / 64, BB), blk>>>(buf1, enc_w2, enc_b2, buf2, H1C, H2C);
    bnstats_exact<<<H2C / 32, 32>>>(buf2, H2C);
    bnrelu_exact<<<(BB * H2C * TT) / 256, 256>>>(buf2, bn2_g, bn2_b, H2C - 1, BB * H2C * TT);

    conv_exact<1><<<dim3(tg, DDIM / 64, BB), blk>>>(buf2, enc_w3, enc_b3, zb, H2C, DDIM);

    // ---- VQ (bitwise d2) ----
    zero_loss_kernel<<<1, 1>>>();
    cnorm_exact<<<(KCODES + 255) / 256, 256>>>(cb);
    vq_exact<<<(BB * TT) / 128, 128>>>(zb, cb, qb, idx_out);

    // ---- decoder (1e-3 tolerance path) ----
    conv_exact<3><<<dim3(tg, H2C / 64, BB), blk>>>(qb, dec_w1, dec_b1, buf1, DDIM, H2C);
    bnstats_fast<<<H2C, 256>>>(buf1, H2C);
    bnrelu_exact<<<(BB * H2C * TT) / 256, 256>>>(buf1, dbn1_g, dbn1_b, H2C - 1, BB * H2C * TT);

    conv_exact<3><<<dim3(tg, H1C / 64, BB), blk>>>(buf1, dec_w2, dec_b2, buf2, H2C, H1C);
    bnstats_fast<<<H1C, 256>>>(buf2, H1C);
    bnrelu_exact<<<(BB * H1C * TT) / 256, 256>>>(buf2, dbn2_g, dbn2_b, H1C - 1, BB * H1C * TT);

    conv_exact<3><<<dim3(tg, 2, BB), blk>>>(buf2, dec_w3, dec_b3, out, H1C, CIN);

    finalize_kernel<<<1, 1>>>(out);
}

// round 6
// speedup vs baseline: 2.1013x; 2.1013x over previous
#include <cuda_runtime.h>

// ---------------- problem constants ----------------
#define BB 16
#define TT 4096
#define CIN 80
#define H1C 128
#define H2C 256
#define DDIM 64
#define KCODES 512

#define REC_ELEMS (BB*CIN*TT)   // 5242880
#define IDX_ELEMS (BB*TT)       // 65536

// ---------------- device scratch (no allocs allowed) ----------------
__device__ float g_buf1[BB*H2C*TT];
__device__ float g_buf2[BB*H2C*TT];
__device__ float g_z  [BB*DDIM*TT];
__device__ float g_q  [BB*DDIM*TT];
__device__ float g_mean[H2C];
__device__ float g_rstd[H2C];
__device__ float g_cnorm[KCODES];
__device__ float g_loss;

// ============================================================
// ENCODER conv1d — BITWISE FROZEN (do not touch):
// per output a single sequential fma chain over k = (kw outer, ci inner);
// zero-pads exact fma no-ops; bias added after as one fadd.
// ============================================================
template<int K>
__global__ __launch_bounds__(256, 2)
void conv_exact(const float* __restrict__ in, const float* __restrict__ w,
                const float* __restrict__ bias, float* __restrict__ out,
                int Ci, int Co)
{
    const int pad = K / 2;
    __shared__ float xs[16][256];
    __shared__ float ws[64][16];

    const int tid = threadIdx.x;
    const int tx = tid & 31;
    const int ty = tid >> 5;
    const int t0  = blockIdx.x * 256;
    const int co0 = blockIdx.y * 64;
    const int b   = blockIdx.z;

    float acc[8][8];
    #pragma unroll
    for (int i = 0; i < 8; i++)
        #pragma unroll
        for (int j = 0; j < 8; j++) acc[i][j] = 0.f;

    const int nchunks = Ci / 16;
    #pragma unroll
    for (int kw = 0; kw < K; kw++) {
        for (int cic = 0; cic < nchunks; ++cic) {
            const int ci0 = cic * 16;
            __syncthreads();
            #pragma unroll
            for (int it = 0; it < 16; it++) {
                int idx = tid + it * 256;
                int r = idx >> 8, col = idx & 255;
                int gt = t0 + col + kw - pad;
                float v = 0.f;
                if (gt >= 0 && gt < TT)
                    v = in[((size_t)(b * Ci + ci0 + r)) * TT + gt];
                xs[r][col] = v;
            }
            {
                int idx = tid;
                #pragma unroll
                for (int it = 0; it < 4; it++, idx += 256) {
                    int cl = idx >> 4, cc = idx & 15;
                    int co = co0 + cl;
                    ws[cl][cc] = (co < Co) ? w[((size_t)co * Ci + ci0 + cc) * K + kw] : 0.f;
                }
            }
            __syncthreads();

            #pragma unroll
            for (int cc = 0; cc < 16; ++cc) {
                float xr[8];
                #pragma unroll
                for (int j = 0; j < 8; j++) xr[j] = xs[cc][tx + 32 * j];
                #pragma unroll
                for (int i = 0; i < 8; i++) {
                    float wv = ws[ty + 8 * i][cc];
                    #pragma unroll
                    for (int j = 0; j < 8; j++)
                        acc[i][j] = __fmaf_rn(xr[j], wv, acc[i][j]);
                }
            }
        }
    }

    #pragma unroll
    for (int i = 0; i < 8; i++) {
        int co = co0 + ty + 8 * i;
        if (co < Co) {
            float bv = bias[co];
            float* op = out + ((size_t)(b * Co + co)) * TT + t0;
            #pragma unroll
            for (int j = 0; j < 8; j++)
                op[tx + 32 * j] = __fadd_rn(acc[i][j], bv);
        }
    }
}

// ============================================================
// DECODER conv1d — fast path (1e-3 tolerance): single halo tile per
// ci-chunk, kw inner, 1/3 the smem traffic + syncs of conv_exact.
// ============================================================
#define XCOLS 258
template<int K>
__global__ __launch_bounds__(256, 2)
void conv_fast(const float* __restrict__ in, const float* __restrict__ w,
               const float* __restrict__ bias, float* __restrict__ out,
               int Ci, int Co)
{
    const int pad = K / 2;
    __shared__ float xs[16][XCOLS];
    __shared__ float ws[64][16 * 3];

    const int tid = threadIdx.x;
    const int tx = tid & 31;
    const int ty = tid >> 5;
    const int t0  = blockIdx.x * 256;
    const int co0 = blockIdx.y * 64;
    const int b   = blockIdx.z;

    float acc[8][8];
    #pragma unroll
    for (int i = 0; i < 8; i++)
        #pragma unroll
        for (int j = 0; j < 8; j++) acc[i][j] = 0.f;

    const int nchunks = Ci / 16;
    for (int ch = 0; ch < nchunks; ++ch) {
        const int ci0 = ch * 16;
        __syncthreads();
        for (int idx = tid; idx < 16 * XCOLS; idx += 256) {
            int r = idx / XCOLS;
            int cpos = idx - r * XCOLS;
            int gt = t0 + cpos - pad;
            float v = 0.f;
            if (gt >= 0 && gt < TT)
                v = in[((size_t)(b * Ci + ci0 + r)) * TT + gt];
            xs[r][cpos] = v;
        }
        for (int idx = tid; idx < 64 * 16 * K; idx += 256) {
            int col  = idx % (16 * K);
            int cl   = idx / (16 * K);
            int cc = col / K;
            int k  = col % K;
            float v = 0.f;
            if (co0 + cl < Co)
                v = w[(((size_t)(co0 + cl)) * Ci + ci0 + cc) * K + k];
            ws[cl][col] = v;
        }
        __syncthreads();

        #pragma unroll
        for (int cc = 0; cc < 16; ++cc) {
            #pragma unroll
            for (int k = 0; k < K; ++k) {
                float xr[8];
                #pragma unroll
                for (int j = 0; j < 8; j++) xr[j] = xs[cc][tx + 32 * j + k];
                #pragma unroll
                for (int i = 0; i < 8; i++) {
                    float wv = ws[ty + 8 * i][cc * K + k];
                    #pragma unroll
                    for (int j = 0; j < 8; j++)
                        acc[i][j] = fmaf(wv, xr[j], acc[i][j]);
                }
            }
        }
    }

    #pragma unroll
    for (int i = 0; i < 8; i++) {
        int co = co0 + ty + 8 * i;
        if (co < Co) {
            float bv = bias[co];
            float* op = out + ((size_t)(b * Co + co)) * TT + t0;
            #pragma unroll
            for (int j = 0; j < 8; j++)
                op[tx + 32 * j] = acc[i][j] + bv;
        }
    }
}

// ============================================================
// ENCODER BN stats — bitwise two-level chain, 16-way parallel:
// lane b computes its 4096-term sequential chain; every lane replays the
// identical ordered 16-term combine via shfl(width=16). Bit-identical to
// the serial version (same adds, same order).
// ============================================================
__global__ __launch_bounds__(256)
void bnstats_par(const float* __restrict__ x, int C)
{
    const int tid = threadIdx.x;
    const int b   = tid & 15;
    const int cl  = tid >> 4;               // 0..15
    const int c   = blockIdx.x * 16 + cl;
    if (c >= C) return;

    const float* p = x + ((size_t)(b * C + c)) * TT;

    // ---- pass 1: per-batch subtotal ----
    float s = 0.f;
    for (int t = 0; t < TT; t += 16) {
        float4 a0 = __ldg((const float4*)(p + t));
        float4 a1 = __ldg((const float4*)(p + t + 4));
        float4 a2 = __ldg((const float4*)(p + t + 8));
        float4 a3 = __ldg((const float4*)(p + t + 12));
        s = __fadd_rn(s, a0.x); s = __fadd_rn(s, a0.y);
        s = __fadd_rn(s, a0.z); s = __fadd_rn(s, a0.w);
        s = __fadd_rn(s, a1.x); s = __fadd_rn(s, a1.y);
        s = __fadd_rn(s, a1.z); s = __fadd_rn(s, a1.w);
        s = __fadd_rn(s, a2.x); s = __fadd_rn(s, a2.y);
        s = __fadd_rn(s, a2.z); s = __fadd_rn(s, a2.w);
        s = __fadd_rn(s, a3.x); s = __fadd_rn(s, a3.y);
        s = __fadd_rn(s, a3.z); s = __fadd_rn(s, a3.w);
    }
    // ordered combine over b ascending (same chain as serial reference)
    float S = 0.f;
    #pragma unroll
    for (int i = 0; i < 16; i++) {
        float v = __shfl_sync(0xffffffffu, s, i, 16);
        S = __fadd_rn(S, v);
    }
    const float m = __fdiv_rn(S, (float)(BB * TT));

    // ---- pass 2: per-batch var subtotal (mul-then-add) ----
    float s2 = 0.f;
    for (int t = 0; t < TT; t += 16) {
        float4 a0 = __ldg((const float4*)(p + t));
        float4 a1 = __ldg((const float4*)(p + t + 4));
        float4 a2 = __ldg((const float4*)(p + t + 8));
        float4 a3 = __ldg((const float4*)(p + t + 12));
        float d;
        d = __fsub_rn(a0.x, m); s2 = __fadd_rn(s2, __fmul_rn(d, d));
        d = __fsub_rn(a0.y, m); s2 = __fadd_rn(s2, __fmul_rn(d, d));
        d = __fsub_rn(a0.z, m); s2 = __fadd_rn(s2, __fmul_rn(d, d));
        d = __fsub_rn(a0.w, m); s2 = __fadd_rn(s2, __fmul_rn(d, d));
        d = __fsub_rn(a1.x, m); s2 = __fadd_rn(s2, __fmul_rn(d, d));
        d = __fsub_rn(a1.y, m); s2 = __fadd_rn(s2, __fmul_rn(d, d));
        d = __fsub_rn(a1.z, m); s2 = __fadd_rn(s2, __fmul_rn(d, d));
        d = __fsub_rn(a1.w, m); s2 = __fadd_rn(s2, __fmul_rn(d, d));
        d = __fsub_rn(a2.x, m); s2 = __fadd_rn(s2, __fmul_rn(d, d));
        d = __fsub_rn(a2.y, m); s2 = __fadd_rn(s2, __fmul_rn(d, d));
        d = __fsub_rn(a2.z, m); s2 = __fadd_rn(s2, __fmul_rn(d, d));
        d = __fsub_rn(a2.w, m); s2 = __fadd_rn(s2, __fmul_rn(d, d));
        d = __fsub_rn(a3.x, m); s2 = __fadd_rn(s2, __fmul_rn(d, d));
        d = __fsub_rn(a3.y, m); s2 = __fadd_rn(s2, __fmul_rn(d, d));
        d = __fsub_rn(a3.z, m); s2 = __fadd_rn(s2, __fmul_rn(d, d));
        d = __fsub_rn(a3.w, m); s2 = __fadd_rn(s2, __fmul_rn(d, d));
    }
    float V = 0.f;
    #pragma unroll
    for (int i = 0; i < 16; i++) {
        float v = __shfl_sync(0xffffffffu, s2, i, 16);
        V = __fadd_rn(V, v);
    }
    if (b == 0) {
        const float var = __fdiv_rn(V, (float)(BB * TT));
        g_mean[c] = m;
        g_rstd[c] = __fdiv_rn(1.0f, __fsqrt_rn(__fadd_rn(var, 1e-5f)));
    }
}

// ---------------- fast parallel BN stats (decoder, 1e-3 path) ----------------
__global__ void bnstats_fast(const float* __restrict__ x, int C)
{
    const int c = blockIdx.x;
    float s = 0.f, s2 = 0.f;
    for (int b = 0; b < BB; b++) {
        const float* p = x + (size_t)(b * C + c) * TT;
        for (int t = threadIdx.x; t < TT; t += 256) {
            float v = p[t];
            s += v; s2 += v * v;
        }
    }
    #pragma unroll
    for (int o = 16; o > 0; o >>= 1) {
        s  += __shfl_down_sync(0xffffffffu, s,  o);
        s2 += __shfl_down_sync(0xffffffffu, s2, o);
    }
    __shared__ float sa[8], sb[8];
    int wrp = threadIdx.x >> 5, ln = threadIdx.x & 31;
    if (ln == 0) { sa[wrp] = s; sb[wrp] = s2; }
    __syncthreads();
    if (threadIdx.x == 0) {
        float ts = 0.f, ts2 = 0.f;
        #pragma unroll
        for (int i = 0; i < 8; i++) { ts += sa[i]; ts2 += sb[i]; }
        const float invn = 1.f / (float)(BB * TT);
        float m = ts * invn;
        float var = ts2 * invn - m * m;
        g_mean[c] = m;
        g_rstd[c] = __fdiv_rn(1.0f, __fsqrt_rn(__fadd_rn(var, 1e-5f)));
    }
}

// ---------------- BN apply + relu: ((x-m)*r)*g + b ----------------
__global__ void bnrelu_exact(float* __restrict__ x, const float* __restrict__ gam,
                             const float* __restrict__ bet, int Cmask, int n)
{
    int i = blockIdx.x * 256 + threadIdx.x;
    if (i >= n) return;
    int c = (i >> 12) & Cmask;
    float v = __fadd_rn(
        __fmul_rn(__fmul_rn(__fsub_rn(x[i], g_mean[c]), g_rstd[c]), gam[c]),
        bet[c]);
    x[i] = v > 0.f ? v : 0.f;
}

// ---------------- VQ ----------------
__global__ void zero_loss_kernel() { g_loss = 0.f; }

__global__ void cnorm_exact(const float* __restrict__ cb)
{
    int c = blockIdx.x * 256 + threadIdx.x;
    if (c >= KCODES) return;
    float s = 0.f;
    #pragma unroll
    for (int d = 0; d < DDIM; d++) {
        float v = cb[c * DDIM + d];
        s = __fadd_rn(s, __fmul_rn(v, v));
    }
    g_cnorm[c] = s;
}

__global__ __launch_bounds__(128)
void vq_exact(const float* __restrict__ z, const float* __restrict__ cb,
              float* __restrict__ q, float* __restrict__ idx_out)
{
    __shared__ __align__(16) float cs[128 * DDIM];
    __shared__ float cn[128];
    __shared__ float red[4];

    const int tid = threadIdx.x;
    const int n = blockIdx.x * 128 + tid;
    const int b = n >> 12;
    const int t = n & (TT - 1);

    float zv[DDIM];
    #pragma unroll
    for (int d = 0; d < DDIM; d++) zv[d] = z[(size_t)(b * DDIM + d) * TT + t];

    float s1 = 0.f;
    #pragma unroll
    for (int d = 0; d < DDIM; d++) s1 = __fadd_rn(s1, __fmul_rn(zv[d], zv[d]));

    float best = 3.402823466e38f;
    int bidx = 0;

    for (int ch = 0; ch < KCODES / 128; ++ch) {
        __syncthreads();
        for (int i = tid; i < 128 * DDIM; i += 128)
            cs[i] = cb[ch * 128 * DDIM + i];
        cn[tid] = g_cnorm[ch * 128 + tid];
        __syncthreads();

        #pragma unroll 4
        for (int c = 0; c < 128; ++c) {
            const float* cv = &cs[c * DDIM];
            float dot = 0.f;
            #pragma unroll
            for (int d = 0; d < DDIM; d++)
                dot = __fmaf_rn(zv[d], cv[d], dot);
            float a  = __fadd_rn(s1, cn[c]);
            float d2 = __fsub_rn(a, __fmul_rn(2.0f, dot));
            if (d2 < best) { best = d2; bidx = ch * 128 + c; }
        }
    }

    idx_out[n] = (float)bidx;

    float lsum = 0.f;
    #pragma unroll
    for (int d = 0; d < DDIM; d++) {
        float cv = cb[bidx * DDIM + d];
        float qst = __fadd_rn(zv[d], __fsub_rn(cv, zv[d]));
        q[(size_t)(b * DDIM + d) * TT + t] = qst;
        float df = cv - zv[d];
        lsum += df * df;
    }
    #pragma unroll
    for (int o = 16; o > 0; o >>= 1)
        lsum += __shfl_down_sync(0xffffffffu, lsum, o);
    if ((tid & 31) == 0) red[tid >> 5] = lsum;
    __syncthreads();
    if (tid == 0)
        atomicAdd(&g_loss, red[0] + red[1] + red[2] + red[3]);
}

__global__ void finalize_kernel(float* __restrict__ out)
{
    out[REC_ELEMS] = 1.25f * g_loss / (float)(BB * TT * DDIM);
}

// ---------------- launch ----------------
extern "C" void kernel_launch(void* const* d_in, const int* in_sizes, int n_in,
                              void* d_out, int out_size)
{
    const float* x      = (const float*)d_in[0];
    const float* enc_w1 = (const float*)d_in[1];
    const float* enc_b1 = (const float*)d_in[2];
    const float* bn1_g  = (const float*)d_in[3];
    const float* bn1_b  = (const float*)d_in[4];
    const float* enc_w2 = (const float*)d_in[5];
    const float* enc_b2 = (const float*)d_in[6];
    const float* bn2_g  = (const float*)d_in[7];
    const float* bn2_b  = (const float*)d_in[8];
    const float* enc_w3 = (const float*)d_in[9];
    const float* enc_b3 = (const float*)d_in[10];
    const float* cb     = (const float*)d_in[11];
    const float* dec_w1 = (const float*)d_in[12];
    const float* dec_b1 = (const float*)d_in[13];
    const float* dbn1_g = (const float*)d_in[14];
    const float* dbn1_b = (const float*)d_in[15];
    const float* dec_w2 = (const float*)d_in[16];
    const float* dec_b2 = (const float*)d_in[17];
    const float* dbn2_g = (const float*)d_in[18];
    const float* dbn2_b = (const float*)d_in[19];
    const float* dec_w3 = (const float*)d_in[20];
    const float* dec_b3 = (const float*)d_in[21];

    float* out = (float*)d_out;
    float* idx_out = out + REC_ELEMS + 1;

    float *buf1, *buf2, *zb, *qb;
    cudaGetSymbolAddress((void**)&buf1, g_buf1);
    cudaGetSymbolAddress((void**)&buf2, g_buf2);
    cudaGetSymbolAddress((void**)&zb,   g_z);
    cudaGetSymbolAddress((void**)&qb,   g_q);

    const dim3 blk(256);
    const int tg = TT / 256;   // 16

    // ---- encoder (bitwise-frozen path) ----
    conv_exact<3><<<dim3(tg, H1C / 64, BB), blk>>>(x, enc_w1, enc_b1, buf1, CIN, H1C);
    bnstats_par<<<H1C / 16, 256>>>(buf1, H1C);
    bnrelu_exact<<<(BB * H1C * TT) / 256, 256>>>(buf1, bn1_g, bn1_b, H1C - 1, BB * H1C * TT);

    conv_exact<3><<<dim3(tg, H2C / 64, BB), blk>>>(buf1, enc_w2, enc_b2, buf2, H1C, H2C);
    bnstats_par<<<H2C / 16, 256>>>(buf2, H2C);
    bnrelu_exact<<<(BB * H2C * TT) / 256, 256>>>(buf2, bn2_g, bn2_b, H2C - 1, BB * H2C * TT);

    conv_exact<1><<<dim3(tg, DDIM / 64, BB), blk>>>(buf2, enc_w3, enc_b3, zb, H2C, DDIM);

    // ---- VQ (bitwise d2) ----
    zero_loss_kernel<<<1, 1>>>();
    cnorm_exact<<<(KCODES + 255) / 256, 256>>>(cb);
    vq_exact<<<(BB * TT) / 128, 128>>>(zb, cb, qb, idx_out);

    // ---- decoder (1e-3 tolerance path, fast conv) ----
    conv_fast<3><<<dim3(tg, H2C / 64, BB), blk>>>(qb, dec_w1, dec_b1, buf1, DDIM, H2C);
    bnstats_fast<<<H2C, 256>>>(buf1, H2C);
    bnrelu_exact<<<(BB * H2C * TT) / 256, 256>>>(buf1, dbn1_g, dbn1_b, H2C - 1, BB * H2C * TT);

    conv_fast<3><<<dim3(tg, H1C / 64, BB), blk>>>(buf1, dec_w2, dec_b2, buf2, H2C, H1C);
    bnstats_fast<<<H1C, 256>>>(buf2, H1C);
    bnrelu_exact<<<(BB * H1C * TT) / 256, 256>>>(buf2, dbn2_g, dbn2_b, H1C - 1, BB * H1C * TT);

    conv_fast<3><<<dim3(tg, 2, BB), blk>>>(buf2, dec_w3, dec_b3, out, H1C, CIN);

    finalize_kernel<<<1, 1>>>(out);
}

// round 7
// speedup vs baseline: 2.1769x; 1.0360x over previous
#include <cuda_runtime.h>

// ---------------- problem constants ----------------
#define BB 16
#define TT 4096
#define CIN 80
#define H1C 128
#define H2C 256
#define DDIM 64
#define KCODES 512

#define REC_ELEMS (BB*CIN*TT)   // 5242880
#define IDX_ELEMS (BB*TT)       // 65536

// ---------------- device scratch (no allocs allowed) ----------------
__device__ float g_buf1[BB*H2C*TT];
__device__ float g_buf2[BB*H2C*TT];
__device__ float g_z  [BB*DDIM*TT];
__device__ float g_q  [BB*DDIM*TT];
__device__ float g_mean[H2C];
__device__ float g_rstd[H2C];
__device__ float g_cnorm[KCODES];
__device__ float g_loss;

// ============================================================
// ENCODER conv1d — bitwise chain (kw outer, ci inner, single fma chain,
// bias fadd after). Vectorized smem access; optional fused BN+ReLU on the
// INPUT during staging (identical scalar formula => bitwise safe; pad
// zeros stay raw zeros, matching reference pad-after-BN).
// Thread column map: j -> tx*4 + (j&3) + 128*(j>>2).
// ============================================================
template<int K, bool FUSE>
__global__ __launch_bounds__(256, 2)
void conv_exact(const float* __restrict__ in, const float* __restrict__ w,
                const float* __restrict__ bias, float* __restrict__ out,
                int Ci, int Co,
                const float* __restrict__ gam, const float* __restrict__ bet)
{
    const int pad = K / 2;
    __shared__ float xs[16][256];
    __shared__ float ws[64][16];

    const int tid = threadIdx.x;
    const int tx = tid & 31;
    const int ty = tid >> 5;
    const int t0  = blockIdx.x * 256;
    const int co0 = blockIdx.y * 64;
    const int b   = blockIdx.z;

    float acc[8][8];
    #pragma unroll
    for (int i = 0; i < 8; i++)
        #pragma unroll
        for (int j = 0; j < 8; j++) acc[i][j] = 0.f;

    const int nchunks = Ci / 16;
    #pragma unroll
    for (int kw = 0; kw < K; kw++) {
        for (int cic = 0; cic < nchunks; ++cic) {
            const int ci0 = cic * 16;
            __syncthreads();
            #pragma unroll
            for (int it = 0; it < 16; it++) {
                int idx = tid + it * 256;
                int r = idx >> 8, col = idx & 255;
                int ci = ci0 + r;
                int gt = t0 + col + kw - pad;
                float v = 0.f;
                if (gt >= 0 && gt < TT) {
                    v = in[((size_t)(b * Ci + ci)) * TT + gt];
                    if (FUSE) {
                        v = __fadd_rn(
                            __fmul_rn(__fmul_rn(__fsub_rn(v, g_mean[ci]), g_rstd[ci]), gam[ci]),
                            bet[ci]);
                        v = v > 0.f ? v : 0.f;
                    }
                }
                xs[r][col] = v;
            }
            {
                int idx = tid;
                #pragma unroll
                for (int it = 0; it < 4; it++, idx += 256) {
                    int cl = idx >> 4, cc = idx & 15;
                    ws[cl][cc] = w[((size_t)(co0 + cl) * Ci + ci0 + cc) * K + kw];
                }
            }
            __syncthreads();

            #pragma unroll
            for (int cc4 = 0; cc4 < 4; ++cc4) {
                float4 w4[8];
                #pragma unroll
                for (int i = 0; i < 8; i++)
                    w4[i] = *(const float4*)&ws[ty + 8 * i][cc4 * 4];
                #pragma unroll
                for (int q = 0; q < 4; ++q) {
                    const int cc = cc4 * 4 + q;
                    float4 xa = *(const float4*)&xs[cc][tx * 4];
                    float4 xb = *(const float4*)&xs[cc][tx * 4 + 128];
                    #pragma unroll
                    for (int i = 0; i < 8; i++) {
                        float wv = (q == 0) ? w4[i].x : (q == 1) ? w4[i].y
                                 : (q == 2) ? w4[i].z : w4[i].w;
                        acc[i][0] = __fmaf_rn(xa.x, wv, acc[i][0]);
                        acc[i][1] = __fmaf_rn(xa.y, wv, acc[i][1]);
                        acc[i][2] = __fmaf_rn(xa.z, wv, acc[i][2]);
                        acc[i][3] = __fmaf_rn(xa.w, wv, acc[i][3]);
                        acc[i][4] = __fmaf_rn(xb.x, wv, acc[i][4]);
                        acc[i][5] = __fmaf_rn(xb.y, wv, acc[i][5]);
                        acc[i][6] = __fmaf_rn(xb.z, wv, acc[i][6]);
                        acc[i][7] = __fmaf_rn(xb.w, wv, acc[i][7]);
                    }
                }
            }
        }
    }

    #pragma unroll
    for (int i = 0; i < 8; i++) {
        int co = co0 + ty + 8 * i;
        float bv = bias[co];
        float* op = out + ((size_t)(b * Co + co)) * TT + t0;
        float4 o0, o1;
        o0.x = __fadd_rn(acc[i][0], bv);
        o0.y = __fadd_rn(acc[i][1], bv);
        o0.z = __fadd_rn(acc[i][2], bv);
        o0.w = __fadd_rn(acc[i][3], bv);
        o1.x = __fadd_rn(acc[i][4], bv);
        o1.y = __fadd_rn(acc[i][5], bv);
        o1.z = __fadd_rn(acc[i][6], bv);
        o1.w = __fadd_rn(acc[i][7], bv);
        *(float4*)&op[tx * 4]       = o0;
        *(float4*)&op[tx * 4 + 128] = o1;
    }
}

// ============================================================
// DECODER conv1d — fast path (1e-3 tolerance). Halo tile staged once per
// ci-chunk; two aligned LDS.128 per column-group cover all 3 k-shifts via
// static component selects. Optional fused BN+ReLU on input.
// ============================================================
template<bool FUSE>
__global__ __launch_bounds__(256, 2)
void conv_fast(const float* __restrict__ in, const float* __restrict__ w,
               const float* __restrict__ bias, float* __restrict__ out,
               int Ci, int Co,
               const float* __restrict__ gam, const float* __restrict__ bet)
{
    __shared__ float xs[16][260];   // smem col c <-> global t0 + c - 1, c in [0,258)
    __shared__ float ws[64][48];    // ws[cl][cc*3+k]

    const int tid = threadIdx.x;
    const int tx = tid & 31;
    const int ty = tid >> 5;
    const int t0  = blockIdx.x * 256;
    const int co0 = blockIdx.y * 64;
    const int b   = blockIdx.z;

    float acc[8][8];
    #pragma unroll
    for (int i = 0; i < 8; i++)
        #pragma unroll
        for (int j = 0; j < 8; j++) acc[i][j] = 0.f;

    const int nchunks = Ci / 16;
    for (int ch = 0; ch < nchunks; ++ch) {
        const int ci0 = ch * 16;
        __syncthreads();
        for (int idx = tid; idx < 16 * 258; idx += 256) {
            int r = idx / 258;
            int c = idx - r * 258;
            int ci = ci0 + r;
            int gt = t0 + c - 1;
            float v = 0.f;
            if (gt >= 0 && gt < TT) {
                v = in[((size_t)(b * Ci + ci)) * TT + gt];
                if (FUSE) {
                    v = __fadd_rn(
                        __fmul_rn(__fmul_rn(__fsub_rn(v, g_mean[ci]), g_rstd[ci]), gam[ci]),
                        bet[ci]);
                    v = v > 0.f ? v : 0.f;
                }
            }
            xs[r][c] = v;
        }
        for (int idx = tid; idx < 64 * 48; idx += 256) {
            int cl  = idx / 48;
            int col = idx - cl * 48;
            int cc = col / 3, k = col - cc * 3;
            int co = co0 + cl;
            ws[cl][col] = (co < Co) ? w[(((size_t)co) * Ci + ci0 + cc) * 3 + k] : 0.f;
        }
        __syncthreads();

        #pragma unroll
        for (int cc = 0; cc < 16; ++cc) {
            float4 a0 = *(const float4*)&xs[cc][tx * 4];
            float4 a1 = *(const float4*)&xs[cc][tx * 4 + 4];
            float4 c0 = *(const float4*)&xs[cc][tx * 4 + 128];
            float4 c1 = *(const float4*)&xs[cc][tx * 4 + 132];
            #pragma unroll
            for (int k = 0; k < 3; ++k) {
                float x0 = (k == 0) ? a0.x : (k == 1) ? a0.y : a0.z;
                float x1 = (k == 0) ? a0.y : (k == 1) ? a0.z : a0.w;
                float x2 = (k == 0) ? a0.z : (k == 1) ? a0.w : a1.x;
                float x3 = (k == 0) ? a0.w : (k == 1) ? a1.x : a1.y;
                float y0 = (k == 0) ? c0.x : (k == 1) ? c0.y : c0.z;
                float y1 = (k == 0) ? c0.y : (k == 1) ? c0.z : c0.w;
                float y2 = (k == 0) ? c0.z : (k == 1) ? c0.w : c1.x;
                float y3 = (k == 0) ? c0.w : (k == 1) ? c1.x : c1.y;
                #pragma unroll
                for (int i = 0; i < 8; i++) {
                    float wv = ws[ty + 8 * i][cc * 3 + k];
                    acc[i][0] = fmaf(x0, wv, acc[i][0]);
                    acc[i][1] = fmaf(x1, wv, acc[i][1]);
                    acc[i][2] = fmaf(x2, wv, acc[i][2]);
                    acc[i][3] = fmaf(x3, wv, acc[i][3]);
                    acc[i][4] = fmaf(y0, wv, acc[i][4]);
                    acc[i][5] = fmaf(y1, wv, acc[i][5]);
                    acc[i][6] = fmaf(y2, wv, acc[i][6]);
                    acc[i][7] = fmaf(y3, wv, acc[i][7]);
                }
            }
        }
    }

    #pragma unroll
    for (int i = 0; i < 8; i++) {
        int co = co0 + ty + 8 * i;
        if (co < Co) {
            float bv = bias[co];
            float* op = out + ((size_t)(b * Co + co)) * TT + t0;
            float4 o0, o1;
            o0.x = acc[i][0] + bv; o0.y = acc[i][1] + bv;
            o0.z = acc[i][2] + bv; o0.w = acc[i][3] + bv;
            o1.x = acc[i][4] + bv; o1.y = acc[i][5] + bv;
            o1.z = acc[i][6] + bv; o1.w = acc[i][7] + bv;
            *(float4*)&op[tx * 4]       = o0;
            *(float4*)&op[tx * 4 + 128] = o1;
        }
    }
}

// ============================================================
// ENCODER BN stats — bitwise two-level chain, 16-way parallel.
// ============================================================
__global__ __launch_bounds__(256)
void bnstats_par(const float* __restrict__ x, int C)
{
    const int tid = threadIdx.x;
    const int b   = tid & 15;
    const int cl  = tid >> 4;
    const int c   = blockIdx.x * 16 + cl;
    if (c >= C) return;

    const float* p = x + ((size_t)(b * C + c)) * TT;

    float s = 0.f;
    for (int t = 0; t < TT; t += 16) {
        float4 a0 = __ldg((const float4*)(p + t));
        float4 a1 = __ldg((const float4*)(p + t + 4));
        float4 a2 = __ldg((const float4*)(p + t + 8));
        float4 a3 = __ldg((const float4*)(p + t + 12));
        s = __fadd_rn(s, a0.x); s = __fadd_rn(s, a0.y);
        s = __fadd_rn(s, a0.z); s = __fadd_rn(s, a0.w);
        s = __fadd_rn(s, a1.x); s = __fadd_rn(s, a1.y);
        s = __fadd_rn(s, a1.z); s = __fadd_rn(s, a1.w);
        s = __fadd_rn(s, a2.x); s = __fadd_rn(s, a2.y);
        s = __fadd_rn(s, a2.z); s = __fadd_rn(s, a2.w);
        s = __fadd_rn(s, a3.x); s = __fadd_rn(s, a3.y);
        s = __fadd_rn(s, a3.z); s = __fadd_rn(s, a3.w);
    }
    float S = 0.f;
    #pragma unroll
    for (int i = 0; i < 16; i++) {
        float v = __shfl_sync(0xffffffffu, s, i, 16);
        S = __fadd_rn(S, v);
    }
    const float m = __fdiv_rn(S, (float)(BB * TT));

    float s2 = 0.f;
    for (int t = 0; t < TT; t += 16) {
        float4 a0 = __ldg((const float4*)(p + t));
        float4 a1 = __ldg((const float4*)(p + t + 4));
        float4 a2 = __ldg((const float4*)(p + t + 8));
        float4 a3 = __ldg((const float4*)(p + t + 12));
        float d;
        d = __fsub_rn(a0.x, m); s2 = __fadd_rn(s2, __fmul_rn(d, d));
        d = __fsub_rn(a0.y, m); s2 = __fadd_rn(s2, __fmul_rn(d, d));
        d = __fsub_rn(a0.z, m); s2 = __fadd_rn(s2, __fmul_rn(d, d));
        d = __fsub_rn(a0.w, m); s2 = __fadd_rn(s2, __fmul_rn(d, d));
        d = __fsub_rn(a1.x, m); s2 = __fadd_rn(s2, __fmul_rn(d, d));
        d = __fsub_rn(a1.y, m); s2 = __fadd_rn(s2, __fmul_rn(d, d));
        d = __fsub_rn(a1.z, m); s2 = __fadd_rn(s2, __fmul_rn(d, d));
        d = __fsub_rn(a1.w, m); s2 = __fadd_rn(s2, __fmul_rn(d, d));
        d = __fsub_rn(a2.x, m); s2 = __fadd_rn(s2, __fmul_rn(d, d));
        d = __fsub_rn(a2.y, m); s2 = __fadd_rn(s2, __fmul_rn(d, d));
        d = __fsub_rn(a2.z, m); s2 = __fadd_rn(s2, __fmul_rn(d, d));
        d = __fsub_rn(a2.w, m); s2 = __fadd_rn(s2, __fmul_rn(d, d));
        d = __fsub_rn(a3.x, m); s2 = __fadd_rn(s2, __fmul_rn(d, d));
        d = __fsub_rn(a3.y, m); s2 = __fadd_rn(s2, __fmul_rn(d, d));
        d = __fsub_rn(a3.z, m); s2 = __fadd_rn(s2, __fmul_rn(d, d));
        d = __fsub_rn(a3.w, m); s2 = __fadd_rn(s2, __fmul_rn(d, d));
    }
    float V = 0.f;
    #pragma unroll
    for (int i = 0; i < 16; i++) {
        float v = __shfl_sync(0xffffffffu, s2, i, 16);
        V = __fadd_rn(V, v);
    }
    if (b == 0) {
        const float var = __fdiv_rn(V, (float)(BB * TT));
        g_mean[c] = m;
        g_rstd[c] = __fdiv_rn(1.0f, __fsqrt_rn(__fadd_rn(var, 1e-5f)));
    }
}

// ---------------- fast parallel BN stats (decoder) ----------------
__global__ void bnstats_fast(const float* __restrict__ x, int C)
{
    const int c = blockIdx.x;
    float s = 0.f, s2 = 0.f;
    for (int b = 0; b < BB; b++) {
        const float* p = x + (size_t)(b * C + c) * TT;
        for (int t = threadIdx.x; t < TT; t += 256) {
            float v = p[t];
            s += v; s2 += v * v;
        }
    }
    #pragma unroll
    for (int o = 16; o > 0; o >>= 1) {
        s  += __shfl_down_sync(0xffffffffu, s,  o);
        s2 += __shfl_down_sync(0xffffffffu, s2, o);
    }
    __shared__ float sa[8], sb[8];
    int wrp = threadIdx.x >> 5, ln = threadIdx.x & 31;
    if (ln == 0) { sa[wrp] = s; sb[wrp] = s2; }
    __syncthreads();
    if (threadIdx.x == 0) {
        float ts = 0.f, ts2 = 0.f;
        #pragma unroll
        for (int i = 0; i < 8; i++) { ts += sa[i]; ts2 += sb[i]; }
        const float invn = 1.f / (float)(BB * TT);
        float m = ts * invn;
        float var = ts2 * invn - m * m;
        g_mean[c] = m;
        g_rstd[c] = __fdiv_rn(1.0f, __fsqrt_rn(__fadd_rn(var, 1e-5f)));
    }
}

// ---------------- VQ ----------------
__global__ void zero_loss_kernel() { g_loss = 0.f; }

__global__ void cnorm_exact(const float* __restrict__ cb)
{
    int c = blockIdx.x * 256 + threadIdx.x;
    if (c >= KCODES) return;
    float s = 0.f;
    #pragma unroll
    for (int d = 0; d < DDIM; d++) {
        float v = cb[c * DDIM + d];
        s = __fadd_rn(s, __fmul_rn(v, v));
    }
    g_cnorm[c] = s;
}

__global__ __launch_bounds__(128)
void vq_exact(const float* __restrict__ z, const float* __restrict__ cb,
              float* __restrict__ q, float* __restrict__ idx_out)
{
    __shared__ __align__(16) float cs[128 * DDIM];
    __shared__ float cn[128];
    __shared__ float red[4];

    const int tid = threadIdx.x;
    const int n = blockIdx.x * 128 + tid;
    const int b = n >> 12;
    const int t = n & (TT - 1);

    float zv[DDIM];
    #pragma unroll
    for (int d = 0; d < DDIM; d++) zv[d] = z[(size_t)(b * DDIM + d) * TT + t];

    float s1 = 0.f;
    #pragma unroll
    for (int d = 0; d < DDIM; d++) s1 = __fadd_rn(s1, __fmul_rn(zv[d], zv[d]));

    float best = 3.402823466e38f;
    int bidx = 0;

    for (int ch = 0; ch < KCODES / 128; ++ch) {
        __syncthreads();
        for (int i = tid; i < 128 * DDIM; i += 128)
            cs[i] = cb[ch * 128 * DDIM + i];
        cn[tid] = g_cnorm[ch * 128 + tid];
        __syncthreads();

        #pragma unroll 4
        for (int c = 0; c < 128; ++c) {
            const float4* cv = (const float4*)&cs[c * DDIM];
            float dot = 0.f;
            #pragma unroll
            for (int d4 = 0; d4 < DDIM / 4; d4++) {
                float4 v = cv[d4];
                dot = __fmaf_rn(zv[4 * d4 + 0], v.x, dot);
                dot = __fmaf_rn(zv[4 * d4 + 1], v.y, dot);
                dot = __fmaf_rn(zv[4 * d4 + 2], v.z, dot);
                dot = __fmaf_rn(zv[4 * d4 + 3], v.w, dot);
            }
            float a  = __fadd_rn(s1, cn[c]);
            float d2 = __fsub_rn(a, __fmul_rn(2.0f, dot));
            if (d2 < best) { best = d2; bidx = ch * 128 + c; }
        }
    }

    idx_out[n] = (float)bidx;

    float lsum = 0.f;
    #pragma unroll
    for (int d = 0; d < DDIM; d++) {
        float cv = cb[bidx * DDIM + d];
        float qst = __fadd_rn(zv[d], __fsub_rn(cv, zv[d]));
        q[(size_t)(b * DDIM + d) * TT + t] = qst;
        float df = cv - zv[d];
        lsum += df * df;
    }
    #pragma unroll
    for (int o = 16; o > 0; o >>= 1)
        lsum += __shfl_down_sync(0xffffffffu, lsum, o);
    if ((tid & 31) == 0) red[tid >> 5] = lsum;
    __syncthreads();
    if (tid == 0)
        atomicAdd(&g_loss, red[0] + red[1] + red[2] + red[3]);
}

__global__ void finalize_kernel(float* __restrict__ out)
{
    out[REC_ELEMS] = 1.25f * g_loss / (float)(BB * TT * DDIM);
}

// ---------------- launch ----------------
extern "C" void kernel_launch(void* const* d_in, const int* in_sizes, int n_in,
                              void* d_out, int out_size)
{
    const float* x      = (const float*)d_in[0];
    const float* enc_w1 = (const float*)d_in[1];
    const float* enc_b1 = (const float*)d_in[2];
    const float* bn1_g  = (const float*)d_in[3];
    const float* bn1_b  = (const float*)d_in[4];
    const float* enc_w2 = (const float*)d_in[5];
    const float* enc_b2 = (const float*)d_in[6];
    const float* bn2_g  = (const float*)d_in[7];
    const float* bn2_b  = (const float*)d_in[8];
    const float* enc_w3 = (const float*)d_in[9];
    const float* enc_b3 = (const float*)d_in[10];
    const float* cb     = (const float*)d_in[11];
    const float* dec_w1 = (const float*)d_in[12];
    const float* dec_b1 = (const float*)d_in[13];
    const float* dbn1_g = (const float*)d_in[14];
    const float* dbn1_b = (const float*)d_in[15];
    const float* dec_w2 = (const float*)d_in[16];
    const float* dec_b2 = (const float*)d_in[17];
    const float* dbn2_g = (const float*)d_in[18];
    const float* dbn2_b = (const float*)d_in[19];
    const float* dec_w3 = (const float*)d_in[20];
    const float* dec_b3 = (const float*)d_in[21];

    float* out = (float*)d_out;
    float* idx_out = out + REC_ELEMS + 1;

    float *buf1, *buf2, *zb, *qb;
    cudaGetSymbolAddress((void**)&buf1, g_buf1);
    cudaGetSymbolAddress((void**)&buf2, g_buf2);
    cudaGetSymbolAddress((void**)&zb,   g_z);
    cudaGetSymbolAddress((void**)&qb,   g_q);

    const dim3 blk(256);
    const int tg = TT / 256;   // 16

    // ---- encoder (bitwise-frozen arithmetic; BN fused into next conv's staging) ----
    conv_exact<3, false><<<dim3(tg, H1C / 64, BB), blk>>>(
        x, enc_w1, enc_b1, buf1, CIN, H1C, nullptr, nullptr);
    bnstats_par<<<H1C / 16, 256>>>(buf1, H1C);

    conv_exact<3, true><<<dim3(tg, H2C / 64, BB), blk>>>(
        buf1, enc_w2, enc_b2, buf2, H1C, H2C, bn1_g, bn1_b);
    bnstats_par<<<H2C / 16, 256>>>(buf2, H2C);

    conv_exact<1, true><<<dim3(tg, DDIM / 64, BB), blk>>>(
        buf2, enc_w3, enc_b3, zb, H2C, DDIM, bn2_g, bn2_b);

    // ---- VQ (bitwise d2) ----
    zero_loss_kernel<<<1, 1>>>();
    cnorm_exact<<<(KCODES + 255) / 256, 256>>>(cb);
    vq_exact<<<(BB * TT) / 128, 128>>>(zb, cb, qb, idx_out);

    // ---- decoder (1e-3 tolerance path) ----
    conv_fast<false><<<dim3(tg, H2C / 64, BB), blk>>>(
        qb, dec_w1, dec_b1, buf1, DDIM, H2C, nullptr, nullptr);
    bnstats_fast<<<H2C, 256>>>(buf1, H2C);

    conv_fast<true><<<dim3(tg, H1C / 64, BB), blk>>>(
        buf1, dec_w2, dec_b2, buf2, H2C, H1C, dbn1_g, dbn1_b);
    bnstats_fast<<<H1C, 256>>>(buf2, H1C);

    conv_fast<true><<<dim3(tg, 2, BB), blk>>>(
        buf2, dec_w3, dec_b3, out, H1C, CIN, dbn2_g, dbn2_b);

    finalize_kernel<<<1, 1>>>(out);
}

// round 12
// speedup vs baseline: 2.4180x; 1.1108x over previous
#include <cuda_runtime.h>

// ---------------- problem constants ----------------
#define BB 16
#define TT 4096
#define CIN 80
#define H1C 128
#define H2C 256
#define DDIM 64
#define KCODES 512

#define REC_ELEMS (BB*CIN*TT)   // 5242880
#define IDX_ELEMS (BB*TT)       // 65536

// ---------------- device scratch (no allocs allowed) ----------------
__device__ float g_buf1[BB*H2C*TT];
__device__ float g_buf2[BB*H2C*TT];
__device__ float g_z  [BB*DDIM*TT];
__device__ float g_q  [BB*DDIM*TT];
__device__ float g_mean[H2C];
__device__ float g_rstd[H2C];
__device__ float g_cnorm[KCODES];
__device__ float g_loss;

// ============================================================
// ENCODER conv1d — bitwise chain (kw outer, ci inner, single fma chain,
// bias fadd after). Vectorized smem access; optional fused BN+ReLU on the
// INPUT during staging (identical scalar formula => bitwise safe; pad
// zeros stay raw zeros, matching reference pad-after-BN).
// ============================================================
template<int K, bool FUSE>
__global__ __launch_bounds__(256, 2)
void conv_exact(const float* __restrict__ in, const float* __restrict__ w,
                const float* __restrict__ bias, float* __restrict__ out,
                int Ci, int Co,
                const float* __restrict__ gam, const float* __restrict__ bet)
{
    const int pad = K / 2;
    __shared__ float xs[16][256];
    __shared__ float ws[64][16];

    const int tid = threadIdx.x;
    const int tx = tid & 31;
    const int ty = tid >> 5;
    const int t0  = blockIdx.x * 256;
    const int co0 = blockIdx.y * 64;
    const int b   = blockIdx.z;

    float acc[8][8];
    #pragma unroll
    for (int i = 0; i < 8; i++)
        #pragma unroll
        for (int j = 0; j < 8; j++) acc[i][j] = 0.f;

    const int nchunks = Ci / 16;
    #pragma unroll
    for (int kw = 0; kw < K; kw++) {
        for (int cic = 0; cic < nchunks; ++cic) {
            const int ci0 = cic * 16;
            __syncthreads();
            #pragma unroll
            for (int it = 0; it < 16; it++) {
                int idx = tid + it * 256;
                int r = idx >> 8, col = idx & 255;
                int ci = ci0 + r;
                int gt = t0 + col + kw - pad;
                float v = 0.f;
                if (gt >= 0 && gt < TT) {
                    v = in[((size_t)(b * Ci + ci)) * TT + gt];
                    if (FUSE) {
                        v = __fadd_rn(
                            __fmul_rn(__fmul_rn(__fsub_rn(v, g_mean[ci]), g_rstd[ci]), gam[ci]),
                            bet[ci]);
                        v = v > 0.f ? v : 0.f;
                    }
                }
                xs[r][col] = v;
            }
            {
                int idx = tid;
                #pragma unroll
                for (int it = 0; it < 4; it++, idx += 256) {
                    int cl = idx >> 4, cc = idx & 15;
                    ws[cl][cc] = w[((size_t)(co0 + cl) * Ci + ci0 + cc) * K + kw];
                }
            }
            __syncthreads();

            #pragma unroll
            for (int cc4 = 0; cc4 < 4; ++cc4) {
                float4 w4[8];
                #pragma unroll
                for (int i = 0; i < 8; i++)
                    w4[i] = *(const float4*)&ws[ty + 8 * i][cc4 * 4];
                #pragma unroll
                for (int q = 0; q < 4; ++q) {
                    const int cc = cc4 * 4 + q;
                    float4 xa = *(const float4*)&xs[cc][tx * 4];
                    float4 xb = *(const float4*)&xs[cc][tx * 4 + 128];
                    #pragma unroll
                    for (int i = 0; i < 8; i++) {
                        float wv = (q == 0) ? w4[i].x : (q == 1) ? w4[i].y
                                 : (q == 2) ? w4[i].z : w4[i].w;
                        acc[i][0] = __fmaf_rn(xa.x, wv, acc[i][0]);
                        acc[i][1] = __fmaf_rn(xa.y, wv, acc[i][1]);
                        acc[i][2] = __fmaf_rn(xa.z, wv, acc[i][2]);
                        acc[i][3] = __fmaf_rn(xa.w, wv, acc[i][3]);
                        acc[i][4] = __fmaf_rn(xb.x, wv, acc[i][4]);
                        acc[i][5] = __fmaf_rn(xb.y, wv, acc[i][5]);
                        acc[i][6] = __fmaf_rn(xb.z, wv, acc[i][6]);
                        acc[i][7] = __fmaf_rn(xb.w, wv, acc[i][7]);
                    }
                }
            }
        }
    }

    #pragma unroll
    for (int i = 0; i < 8; i++) {
        int co = co0 + ty + 8 * i;
        float bv = bias[co];
        float* op = out + ((size_t)(b * Co + co)) * TT + t0;
        float4 o0, o1;
        o0.x = __fadd_rn(acc[i][0], bv);
        o0.y = __fadd_rn(acc[i][1], bv);
        o0.z = __fadd_rn(acc[i][2], bv);
        o0.w = __fadd_rn(acc[i][3], bv);
        o1.x = __fadd_rn(acc[i][4], bv);
        o1.y = __fadd_rn(acc[i][5], bv);
        o1.z = __fadd_rn(acc[i][6], bv);
        o1.w = __fadd_rn(acc[i][7], bv);
        *(float4*)&op[tx * 4]       = o0;
        *(float4*)&op[tx * 4 + 128] = o1;
    }
}

// ============================================================
// DECODER conv1d — fast path (1e-3 tolerance).
// ============================================================
template<bool FUSE>
__global__ __launch_bounds__(256, 2)
void conv_fast(const float* __restrict__ in, const float* __restrict__ w,
               const float* __restrict__ bias, float* __restrict__ out,
               int Ci, int Co,
               const float* __restrict__ gam, const float* __restrict__ bet)
{
    __shared__ float xs[16][260];
    __shared__ float ws[64][48];

    const int tid = threadIdx.x;
    const int tx = tid & 31;
    const int ty = tid >> 5;
    const int t0  = blockIdx.x * 256;
    const int co0 = blockIdx.y * 64;
    const int b   = blockIdx.z;

    float acc[8][8];
    #pragma unroll
    for (int i = 0; i < 8; i++)
        #pragma unroll
        for (int j = 0; j < 8; j++) acc[i][j] = 0.f;

    const int nchunks = Ci / 16;
    for (int ch = 0; ch < nchunks; ++ch) {
        const int ci0 = ch * 16;
        __syncthreads();
        for (int idx = tid; idx < 16 * 258; idx += 256) {
            int r = idx / 258;
            int c = idx - r * 258;
            int ci = ci0 + r;
            int gt = t0 + c - 1;
            float v = 0.f;
            if (gt >= 0 && gt < TT) {
                v = in[((size_t)(b * Ci + ci)) * TT + gt];
                if (FUSE) {
                    v = __fadd_rn(
                        __fmul_rn(__fmul_rn(__fsub_rn(v, g_mean[ci]), g_rstd[ci]), gam[ci]),
                        bet[ci]);
                    v = v > 0.f ? v : 0.f;
                }
            }
            xs[r][c] = v;
        }
        for (int idx = tid; idx < 64 * 48; idx += 256) {
            int cl  = idx / 48;
            int col = idx - cl * 48;
            int cc = col / 3, k = col - cc * 3;
            int co = co0 + cl;
            ws[cl][col] = (co < Co) ? w[(((size_t)co) * Ci + ci0 + cc) * 3 + k] : 0.f;
        }
        __syncthreads();

        #pragma unroll
        for (int cc = 0; cc < 16; ++cc) {
            float4 a0 = *(const float4*)&xs[cc][tx * 4];
            float4 a1 = *(const float4*)&xs[cc][tx * 4 + 4];
            float4 c0 = *(const float4*)&xs[cc][tx * 4 + 128];
            float4 c1 = *(const float4*)&xs[cc][tx * 4 + 132];
            #pragma unroll
            for (int k = 0; k < 3; ++k) {
                float x0 = (k == 0) ? a0.x : (k == 1) ? a0.y : a0.z;
                float x1 = (k == 0) ? a0.y : (k == 1) ? a0.z : a0.w;
                float x2 = (k == 0) ? a0.z : (k == 1) ? a0.w : a1.x;
                float x3 = (k == 0) ? a0.w : (k == 1) ? a1.x : a1.y;
                float y0 = (k == 0) ? c0.x : (k == 1) ? c0.y : c0.z;
                float y1 = (k == 0) ? c0.y : (k == 1) ? c0.z : c0.w;
                float y2 = (k == 0) ? c0.z : (k == 1) ? c0.w : c1.x;
                float y3 = (k == 0) ? c0.w : (k == 1) ? c1.x : c1.y;
                #pragma unroll
                for (int i = 0; i < 8; i++) {
                    float wv = ws[ty + 8 * i][cc * 3 + k];
                    acc[i][0] = fmaf(x0, wv, acc[i][0]);
                    acc[i][1] = fmaf(x1, wv, acc[i][1]);
                    acc[i][2] = fmaf(x2, wv, acc[i][2]);
                    acc[i][3] = fmaf(x3, wv, acc[i][3]);
                    acc[i][4] = fmaf(y0, wv, acc[i][4]);
                    acc[i][5] = fmaf(y1, wv, acc[i][5]);
                    acc[i][6] = fmaf(y2, wv, acc[i][6]);
                    acc[i][7] = fmaf(y3, wv, acc[i][7]);
                }
            }
        }
    }

    #pragma unroll
    for (int i = 0; i < 8; i++) {
        int co = co0 + ty + 8 * i;
        if (co < Co) {
            float bv = bias[co];
            float* op = out + ((size_t)(b * Co + co)) * TT + t0;
            float4 o0, o1;
            o0.x = acc[i][0] + bv; o0.y = acc[i][1] + bv;
            o0.z = acc[i][2] + bv; o0.w = acc[i][3] + bv;
            o1.x = acc[i][4] + bv; o1.y = acc[i][5] + bv;
            o1.z = acc[i][6] + bv; o1.w = acc[i][7] + bv;
            *(float4*)&op[tx * 4]       = o0;
            *(float4*)&op[tx * 4 + 128] = o1;
        }
    }
}

// ============================================================
// ENCODER BN stats — bitwise two-level chain, spread wide:
// blockDim=64 (4 channels/block), grid=C/4 blocks -> 32..64 SMs busy.
// Lane b of each 16-lane group owns batch b's 4096-term chain; ordered
// 16-term shfl combine replays the reference's serial sum. Bit-identical.
// ============================================================
__global__ __launch_bounds__(64)
void bnstats_par(const float* __restrict__ x, int C)
{
    const int tid = threadIdx.x;
    const int b   = tid & 15;
    const int cl  = tid >> 4;               // 0..3
    const int c   = blockIdx.x * 4 + cl;
    if (c >= C) return;

    const float* p = x + ((size_t)(b * C + c)) * TT;

    float s = 0.f;
    for (int t = 0; t < TT; t += 32) {
        float4 v[8];
        #pragma unroll
        for (int u = 0; u < 8; u++) v[u] = __ldg((const float4*)(p + t + 4 * u));
        #pragma unroll
        for (int u = 0; u < 8; u++) {
            s = __fadd_rn(s, v[u].x); s = __fadd_rn(s, v[u].y);
            s = __fadd_rn(s, v[u].z); s = __fadd_rn(s, v[u].w);
        }
    }
    float S = 0.f;
    #pragma unroll
    for (int i = 0; i < 16; i++) {
        float v = __shfl_sync(0xffffffffu, s, i, 16);
        S = __fadd_rn(S, v);
    }
    const float m = __fdiv_rn(S, (float)(BB * TT));

    float s2 = 0.f;
    for (int t = 0; t < TT; t += 32) {
        float4 v[8];
        #pragma unroll
        for (int u = 0; u < 8; u++) v[u] = __ldg((const float4*)(p + t + 4 * u));
        #pragma unroll
        for (int u = 0; u < 8; u++) {
            float d;
            d = __fsub_rn(v[u].x, m); s2 = __fadd_rn(s2, __fmul_rn(d, d));
            d = __fsub_rn(v[u].y, m); s2 = __fadd_rn(s2, __fmul_rn(d, d));
            d = __fsub_rn(v[u].z, m); s2 = __fadd_rn(s2, __fmul_rn(d, d));
            d = __fsub_rn(v[u].w, m); s2 = __fadd_rn(s2, __fmul_rn(d, d));
        }
    }
    float V = 0.f;
    #pragma unroll
    for (int i = 0; i < 16; i++) {
        float v = __shfl_sync(0xffffffffu, s2, i, 16);
        V = __fadd_rn(V, v);
    }
    if (b == 0) {
        const float var = __fdiv_rn(V, (float)(BB * TT));
        g_mean[c] = m;
        g_rstd[c] = __fdiv_rn(1.0f, __fsqrt_rn(__fadd_rn(var, 1e-5f)));
    }
}

// ---------------- fast parallel BN stats (decoder) ----------------
__global__ void bnstats_fast(const float* __restrict__ x, int C)
{
    const int c = blockIdx.x;
    float s = 0.f, s2 = 0.f;
    for (int b = 0; b < BB; b++) {
        const float* p = x + (size_t)(b * C + c) * TT;
        for (int t = threadIdx.x; t < TT; t += 256) {
            float v = p[t];
            s += v; s2 += v * v;
        }
    }
    #pragma unroll
    for (int o = 16; o > 0; o >>= 1) {
        s  += __shfl_down_sync(0xffffffffu, s,  o);
        s2 += __shfl_down_sync(0xffffffffu, s2, o);
    }
    __shared__ float sa[8], sb[8];
    int wrp = threadIdx.x >> 5, ln = threadIdx.x & 31;
    if (ln == 0) { sa[wrp] = s; sb[wrp] = s2; }
    __syncthreads();
    if (threadIdx.x == 0) {
        float ts = 0.f, ts2 = 0.f;
        #pragma unroll
        for (int i = 0; i < 8; i++) { ts += sa[i]; ts2 += sb[i]; }
        const float invn = 1.f / (float)(BB * TT);
        float m = ts * invn;
        float var = ts2 * invn - m * m;
        g_mean[c] = m;
        g_rstd[c] = __fdiv_rn(1.0f, __fsqrt_rn(__fadd_rn(var, 1e-5f)));
    }
}

// ---------------- VQ ----------------
__global__ void zero_loss_kernel() { g_loss = 0.f; }

__global__ void cnorm_exact(const float* __restrict__ cb)
{
    int c = blockIdx.x * 256 + threadIdx.x;
    if (c >= KCODES) return;
    float s = 0.f;
    #pragma unroll
    for (int d = 0; d < DDIM; d++) {
        float v = cb[c * DDIM + d];
        s = __fadd_rn(s, __fmul_rn(v, v));
    }
    g_cnorm[c] = s;
}

__global__ __launch_bounds__(128)
void vq_exact(const float* __restrict__ z, const float* __restrict__ cb,
              float* __restrict__ q, float* __restrict__ idx_out)
{
    __shared__ __align__(16) float cs[128 * DDIM];
    __shared__ float cn[128];
    __shared__ float red[4];

    const int tid = threadIdx.x;
    const int n = blockIdx.x * 128 + tid;
    const int b = n >> 12;
    const int t = n & (TT - 1);

    float zv[DDIM];
    #pragma unroll
    for (int d = 0; d < DDIM; d++) zv[d] = z[(size_t)(b * DDIM + d) * TT + t];

    float s1 = 0.f;
    #pragma unroll
    for (int d = 0; d < DDIM; d++) s1 = __fadd_rn(s1, __fmul_rn(zv[d], zv[d]));

    float best = 3.402823466e38f;
    int bidx = 0;

    for (int ch = 0; ch < KCODES / 128; ++ch) {
        __syncthreads();
        for (int i = tid; i < 128 * DDIM; i += 128)
            cs[i] = cb[ch * 128 * DDIM + i];
        cn[tid] = g_cnorm[ch * 128 + tid];
        __syncthreads();

        #pragma unroll 4
        for (int c = 0; c < 128; ++c) {
            const float4* cv = (const float4*)&cs[c * DDIM];
            float dot = 0.f;
            #pragma unroll
            for (int d4 = 0; d4 < DDIM / 4; d4++) {
                float4 v = cv[d4];
                dot = __fmaf_rn(zv[4 * d4 + 0], v.x, dot);
                dot = __fmaf_rn(zv[4 * d4 + 1], v.y, dot);
                dot = __fmaf_rn(zv[4 * d4 + 2], v.z, dot);
                dot = __fmaf_rn(zv[4 * d4 + 3], v.w, dot);
            }
            float a  = __fadd_rn(s1, cn[c]);
            float d2 = __fsub_rn(a, __fmul_rn(2.0f, dot));
            if (d2 < best) { best = d2; bidx = ch * 128 + c; }
        }
    }

    idx_out[n] = (float)bidx;

    float lsum = 0.f;
    #pragma unroll
    for (int d = 0; d < DDIM; d++) {
        float cv = cb[bidx * DDIM + d];
        float qst = __fadd_rn(zv[d], __fsub_rn(cv, zv[d]));
        q[(size_t)(b * DDIM + d) * TT + t] = qst;
        float df = cv - zv[d];
        lsum += df * df;
    }
    #pragma unroll
    for (int o = 16; o > 0; o >>= 1)
        lsum += __shfl_down_sync(0xffffffffu, lsum, o);
    if ((tid & 31) == 0) red[tid >> 5] = lsum;
    __syncthreads();
    if (tid == 0)
        atomicAdd(&g_loss, red[0] + red[1] + red[2] + red[3]);
}

__global__ void finalize_kernel(float* __restrict__ out)
{
    out[REC_ELEMS] = 1.25f * g_loss / (float)(BB * TT * DDIM);
}

// ---------------- launch ----------------
extern "C" void kernel_launch(void* const* d_in, const int* in_sizes, int n_in,
                              void* d_out, int out_size)
{
    const float* x      = (const float*)d_in[0];
    const float* enc_w1 = (const float*)d_in[1];
    const float* enc_b1 = (const float*)d_in[2];
    const float* bn1_g  = (const float*)d_in[3];
    const float* bn1_b  = (const float*)d_in[4];
    const float* enc_w2 = (const float*)d_in[5];
    const float* enc_b2 = (const float*)d_in[6];
    const float* bn2_g  = (const float*)d_in[7];
    const float* bn2_b  = (const float*)d_in[8];
    const float* enc_w3 = (const float*)d_in[9];
    const float* enc_b3 = (const float*)d_in[10];
    const float* cb     = (const float*)d_in[11];
    const float* dec_w1 = (const float*)d_in[12];
    const float* dec_b1 = (const float*)d_in[13];
    const float* dbn1_g = (const float*)d_in[14];
    const float* dbn1_b = (const float*)d_in[15];
    const float* dec_w2 = (const float*)d_in[16];
    const float* dec_b2 = (const float*)d_in[17];
    const float* dbn2_g = (const float*)d_in[18];
    const float* dbn2_b = (const float*)d_in[19];
    const float* dec_w3 = (const float*)d_in[20];
    const float* dec_b3 = (const float*)d_in[21];

    float* out = (float*)d_out;
    float* idx_out = out + REC_ELEMS + 1;

    float *buf1, *buf2, *zb, *qb;
    cudaGetSymbolAddress((void**)&buf1, g_buf1);
    cudaGetSymbolAddress((void**)&buf2, g_buf2);
    cudaGetSymbolAddress((void**)&zb,   g_z);
    cudaGetSymbolAddress((void**)&qb,   g_q);

    const dim3 blk(256);
    const int tg = TT / 256;   // 16

    // ---- encoder (bitwise-frozen arithmetic; BN fused into next conv's staging) ----
    conv_exact<3, false><<<dim3(tg, H1C / 64, BB), blk>>>(
        x, enc_w1, enc_b1, buf1, CIN, H1C, nullptr, nullptr);
    bnstats_par<<<H1C / 4, 64>>>(buf1, H1C);

    conv_exact<3, true><<<dim3(tg, H2C / 64, BB), blk>>>(
        buf1, enc_w2, enc_b2, buf2, H1C, H2C, bn1_g, bn1_b);
    bnstats_par<<<H2C / 4, 64>>>(buf2, H2C);

    conv_exact<1, true><<<dim3(tg, DDIM / 64, BB), blk>>>(
        buf2, enc_w3, enc_b3, zb, H2C, DDIM, bn2_g, bn2_b);

    // ---- VQ (bitwise d2) ----
    zero_loss_kernel<<<1, 1>>>();
    cnorm_exact<<<(KCODES + 255) / 256, 256>>>(cb);
    vq_exact<<<(BB * TT) / 128, 128>>>(zb, cb, qb, idx_out);

    // ---- decoder (1e-3 tolerance path) ----
    conv_fast<false><<<dim3(tg, H2C / 64, BB), blk>>>(
        qb, dec_w1, dec_b1, buf1, DDIM, H2C, nullptr, nullptr);
    bnstats_fast<<<H2C, 256>>>(buf1, H2C);

    conv_fast<true><<<dim3(tg, H1C / 64, BB), blk>>>(
        buf1, dec_w2, dec_b2, buf2, H2C, H1C, dbn1_g, dbn1_b);
    bnstats_fast<<<H1C, 256>>>(buf2, H1C);

    conv_fast<true><<<dim3(tg, 2, BB), blk>>>(
        buf2, dec_w3, dec_b3, out, H1C, CIN, dbn2_g, dbn2_b);

    finalize_kernel<<<1, 1>>>(out);
}

// round 13
// speedup vs baseline: 2.6351x; 1.0898x over previous
#include <cuda_runtime.h>

// ---------------- problem constants ----------------
#define BB 16
#define TT 4096
#define CIN 80
#define H1C 128
#define H2C 256
#define DDIM 64
#define KCODES 512

#define REC_ELEMS (BB*CIN*TT)   // 5242880
#define IDX_ELEMS (BB*TT)       // 65536

// ---------------- device scratch (no allocs allowed) ----------------
__device__ float g_buf1[BB*H2C*TT];
__device__ float g_buf2[BB*H2C*TT];
__device__ float g_z  [BB*DDIM*TT];
__device__ float g_q  [BB*DDIM*TT];
__device__ float g_mean[H2C];
__device__ float g_rstd[H2C];
__device__ float g_cnorm[KCODES];
__device__ float g_loss;

// ============================================================
// ENCODER conv1d — bitwise chain (kw outer, ci inner, single fma chain,
// bias fadd after). Vectorized smem access; optional fused BN+ReLU on the
// INPUT during staging (identical scalar formula => bitwise safe; pad
// zeros stay raw zeros, matching reference pad-after-BN).
// ============================================================
template<int K, bool FUSE>
__global__ __launch_bounds__(256, 2)
void conv_exact(const float* __restrict__ in, const float* __restrict__ w,
                const float* __restrict__ bias, float* __restrict__ out,
                int Ci, int Co,
                const float* __restrict__ gam, const float* __restrict__ bet)
{
    const int pad = K / 2;
    __shared__ float xs[16][256];
    __shared__ float ws[64][16];

    const int tid = threadIdx.x;
    const int tx = tid & 31;
    const int ty = tid >> 5;
    const int t0  = blockIdx.x * 256;
    const int co0 = blockIdx.y * 64;
    const int b   = blockIdx.z;

    float acc[8][8];
    #pragma unroll
    for (int i = 0; i < 8; i++)
        #pragma unroll
        for (int j = 0; j < 8; j++) acc[i][j] = 0.f;

    const int nchunks = Ci / 16;
    #pragma unroll
    for (int kw = 0; kw < K; kw++) {
        for (int cic = 0; cic < nchunks; ++cic) {
            const int ci0 = cic * 16;
            __syncthreads();
            #pragma unroll
            for (int it = 0; it < 16; it++) {
                int idx = tid + it * 256;
                int r = idx >> 8, col = idx & 255;
                int ci = ci0 + r;
                int gt = t0 + col + kw - pad;
                float v = 0.f;
                if (gt >= 0 && gt < TT) {
                    v = in[((size_t)(b * Ci + ci)) * TT + gt];
                    if (FUSE) {
                        v = __fadd_rn(
                            __fmul_rn(__fmul_rn(__fsub_rn(v, g_mean[ci]), g_rstd[ci]), gam[ci]),
                            bet[ci]);
                        v = v > 0.f ? v : 0.f;
                    }
                }
                xs[r][col] = v;
            }
            {
                int idx = tid;
                #pragma unroll
                for (int it = 0; it < 4; it++, idx += 256) {
                    int cl = idx >> 4, cc = idx & 15;
                    ws[cl][cc] = w[((size_t)(co0 + cl) * Ci + ci0 + cc) * K + kw];
                }
            }
            __syncthreads();

            #pragma unroll
            for (int cc4 = 0; cc4 < 4; ++cc4) {
                float4 w4[8];
                #pragma unroll
                for (int i = 0; i < 8; i++)
                    w4[i] = *(const float4*)&ws[ty + 8 * i][cc4 * 4];
                #pragma unroll
                for (int q = 0; q < 4; ++q) {
                    const int cc = cc4 * 4 + q;
                    float4 xa = *(const float4*)&xs[cc][tx * 4];
                    float4 xb = *(const float4*)&xs[cc][tx * 4 + 128];
                    #pragma unroll
                    for (int i = 0; i < 8; i++) {
                        float wv = (q == 0) ? w4[i].x : (q == 1) ? w4[i].y
                                 : (q == 2) ? w4[i].z : w4[i].w;
                        acc[i][0] = __fmaf_rn(xa.x, wv, acc[i][0]);
                        acc[i][1] = __fmaf_rn(xa.y, wv, acc[i][1]);
                        acc[i][2] = __fmaf_rn(xa.z, wv, acc[i][2]);
                        acc[i][3] = __fmaf_rn(xa.w, wv, acc[i][3]);
                        acc[i][4] = __fmaf_rn(xb.x, wv, acc[i][4]);
                        acc[i][5] = __fmaf_rn(xb.y, wv, acc[i][5]);
                        acc[i][6] = __fmaf_rn(xb.z, wv, acc[i][6]);
                        acc[i][7] = __fmaf_rn(xb.w, wv, acc[i][7]);
                    }
                }
            }
        }
    }

    #pragma unroll
    for (int i = 0; i < 8; i++) {
        int co = co0 + ty + 8 * i;
        float bv = bias[co];
        float* op = out + ((size_t)(b * Co + co)) * TT + t0;
        float4 o0, o1;
        o0.x = __fadd_rn(acc[i][0], bv);
        o0.y = __fadd_rn(acc[i][1], bv);
        o0.z = __fadd_rn(acc[i][2], bv);
        o0.w = __fadd_rn(acc[i][3], bv);
        o1.x = __fadd_rn(acc[i][4], bv);
        o1.y = __fadd_rn(acc[i][5], bv);
        o1.z = __fadd_rn(acc[i][6], bv);
        o1.w = __fadd_rn(acc[i][7], bv);
        *(float4*)&op[tx * 4]       = o0;
        *(float4*)&op[tx * 4 + 128] = o1;
    }
}

// ============================================================
// DECODER conv1d — fast path (1e-3 tolerance).
// ============================================================
template<bool FUSE>
__global__ __launch_bounds__(256, 2)
void conv_fast(const float* __restrict__ in, const float* __restrict__ w,
               const float* __restrict__ bias, float* __restrict__ out,
               int Ci, int Co,
               const float* __restrict__ gam, const float* __restrict__ bet)
{
    __shared__ float xs[16][260];
    __shared__ float ws[64][48];

    const int tid = threadIdx.x;
    const int tx = tid & 31;
    const int ty = tid >> 5;
    const int t0  = blockIdx.x * 256;
    const int co0 = blockIdx.y * 64;
    const int b   = blockIdx.z;

    float acc[8][8];
    #pragma unroll
    for (int i = 0; i < 8; i++)
        #pragma unroll
        for (int j = 0; j < 8; j++) acc[i][j] = 0.f;

    const int nchunks = Ci / 16;
    for (int ch = 0; ch < nchunks; ++ch) {
        const int ci0 = ch * 16;
        __syncthreads();
        for (int idx = tid; idx < 16 * 258; idx += 256) {
            int r = idx / 258;
            int c = idx - r * 258;
            int ci = ci0 + r;
            int gt = t0 + c - 1;
            float v = 0.f;
            if (gt >= 0 && gt < TT) {
                v = in[((size_t)(b * Ci + ci)) * TT + gt];
                if (FUSE) {
                    v = __fadd_rn(
                        __fmul_rn(__fmul_rn(__fsub_rn(v, g_mean[ci]), g_rstd[ci]), gam[ci]),
                        bet[ci]);
                    v = v > 0.f ? v : 0.f;
                }
            }
            xs[r][c] = v;
        }
        for (int idx = tid; idx < 64 * 48; idx += 256) {
            int cl  = idx / 48;
            int col = idx - cl * 48;
            int cc = col / 3, k = col - cc * 3;
            int co = co0 + cl;
            ws[cl][col] = (co < Co) ? w[(((size_t)co) * Ci + ci0 + cc) * 3 + k] : 0.f;
        }
        __syncthreads();

        #pragma unroll
        for (int cc = 0; cc < 16; ++cc) {
            float4 a0 = *(const float4*)&xs[cc][tx * 4];
            float4 a1 = *(const float4*)&xs[cc][tx * 4 + 4];
            float4 c0 = *(const float4*)&xs[cc][tx * 4 + 128];
            float4 c1 = *(const float4*)&xs[cc][tx * 4 + 132];
            #pragma unroll
            for (int k = 0; k < 3; ++k) {
                float x0 = (k == 0) ? a0.x : (k == 1) ? a0.y : a0.z;
                float x1 = (k == 0) ? a0.y : (k == 1) ? a0.z : a0.w;
                float x2 = (k == 0) ? a0.z : (k == 1) ? a0.w : a1.x;
                float x3 = (k == 0) ? a0.w : (k == 1) ? a1.x : a1.y;
                float y0 = (k == 0) ? c0.x : (k == 1) ? c0.y : c0.z;
                float y1 = (k == 0) ? c0.y : (k == 1) ? c0.z : c0.w;
                float y2 = (k == 0) ? c0.z : (k == 1) ? c0.w : c1.x;
                float y3 = (k == 0) ? c0.w : (k == 1) ? c1.x : c1.y;
                #pragma unroll
                for (int i = 0; i < 8; i++) {
                    float wv = ws[ty + 8 * i][cc * 3 + k];
                    acc[i][0] = fmaf(x0, wv, acc[i][0]);
                    acc[i][1] = fmaf(x1, wv, acc[i][1]);
                    acc[i][2] = fmaf(x2, wv, acc[i][2]);
                    acc[i][3] = fmaf(x3, wv, acc[i][3]);
                    acc[i][4] = fmaf(y0, wv, acc[i][4]);
                    acc[i][5] = fmaf(y1, wv, acc[i][5]);
                    acc[i][6] = fmaf(y2, wv, acc[i][6]);
                    acc[i][7] = fmaf(y3, wv, acc[i][7]);
                }
            }
        }
    }

    #pragma unroll
    for (int i = 0; i < 8; i++) {
        int co = co0 + ty + 8 * i;
        if (co < Co) {
            float bv = bias[co];
            float* op = out + ((size_t)(b * Co + co)) * TT + t0;
            float4 o0, o1;
            o0.x = acc[i][0] + bv; o0.y = acc[i][1] + bv;
            o0.z = acc[i][2] + bv; o0.w = acc[i][3] + bv;
            o1.x = acc[i][4] + bv; o1.y = acc[i][5] + bv;
            o1.z = acc[i][6] + bv; o1.w = acc[i][7] + bv;
            *(float4*)&op[tx * 4]       = o0;
            *(float4*)&op[tx * 4 + 128] = o1;
        }
    }
}

// ============================================================
// ENCODER BN stats — warp-per-chain, coalesced smem staging.
// Block = 512 threads = 16 warps, one block per channel c.
// Warp w owns batch b=w: stages 512-float chunks coalesced into its smem
// row; lane 0 replays the sequential fadd chain (t ascending). Warp
// subtotals combined by thread 0 in b-ascending order. Pass 2 stages
// (x-m)^2 (per-element ops identical regardless of computing lane) and
// chains the same way. BIT-IDENTICAL to the reference's two-level reduce.
// ============================================================
__global__ __launch_bounds__(512)
void bnstats_warpchain(const float* __restrict__ x, int C)
{
    __shared__ float buf[16][520];   // 520*4=2080 B row stride (16B aligned)
    __shared__ float wsub[16];
    __shared__ float mbc;

    const int c = blockIdx.x;
    const int w = threadIdx.x >> 5;      // batch index
    const int l = threadIdx.x & 31;
    const float* p = x + ((size_t)(w * C + c)) * TT;

    // ---- pass 1: per-batch sequential sum ----
    float s = 0.f;
    for (int ch = 0; ch < TT / 512; ++ch) {
        const float* q = p + ch * 512;
        #pragma unroll
        for (int u = 0; u < 4; u++) {
            float4 v = __ldg((const float4*)(q + u * 128 + l * 4));
            *(float4*)&buf[w][u * 128 + l * 4] = v;
        }
        __syncwarp();
        if (l == 0) {
            #pragma unroll 16
            for (int i = 0; i < 512; i++) s = __fadd_rn(s, buf[w][i]);
        }
        __syncwarp();
    }
    if (l == 0) wsub[w] = s;
    __syncthreads();
    if (threadIdx.x == 0) {
        float S = 0.f;
        #pragma unroll
        for (int i = 0; i < 16; i++) S = __fadd_rn(S, wsub[i]);
        mbc = __fdiv_rn(S, (float)(BB * TT));
    }
    __syncthreads();
    const float m = mbc;

    // ---- pass 2: per-batch sequential sum of (x-m)^2 ----
    float s2 = 0.f;
    for (int ch = 0; ch < TT / 512; ++ch) {
        const float* q = p + ch * 512;
        #pragma unroll
        for (int u = 0; u < 4; u++) {
            float4 v = __ldg((const float4*)(q + u * 128 + l * 4));
            float4 sq; float d;
            d = __fsub_rn(v.x, m); sq.x = __fmul_rn(d, d);
            d = __fsub_rn(v.y, m); sq.y = __fmul_rn(d, d);
            d = __fsub_rn(v.z, m); sq.z = __fmul_rn(d, d);
            d = __fsub_rn(v.w, m); sq.w = __fmul_rn(d, d);
            *(float4*)&buf[w][u * 128 + l * 4] = sq;
        }
        __syncwarp();
        if (l == 0) {
            #pragma unroll 16
            for (int i = 0; i < 512; i++) s2 = __fadd_rn(s2, buf[w][i]);
        }
        __syncwarp();
    }
    if (l == 0) wsub[w] = s2;
    __syncthreads();
    if (threadIdx.x == 0) {
        float V = 0.f;
        #pragma unroll
        for (int i = 0; i < 16; i++) V = __fadd_rn(V, wsub[i]);
        const float var = __fdiv_rn(V, (float)(BB * TT));
        g_mean[c] = m;
        g_rstd[c] = __fdiv_rn(1.0f, __fsqrt_rn(__fadd_rn(var, 1e-5f)));
    }
}

// ---------------- fast parallel BN stats (decoder) ----------------
__global__ void bnstats_fast(const float* __restrict__ x, int C)
{
    const int c = blockIdx.x;
    float s = 0.f, s2 = 0.f;
    for (int b = 0; b < BB; b++) {
        const float* p = x + (size_t)(b * C + c) * TT;
        for (int t = threadIdx.x; t < TT; t += 256) {
            float v = p[t];
            s += v; s2 += v * v;
        }
    }
    #pragma unroll
    for (int o = 16; o > 0; o >>= 1) {
        s  += __shfl_down_sync(0xffffffffu, s,  o);
        s2 += __shfl_down_sync(0xffffffffu, s2, o);
    }
    __shared__ float sa[8], sb[8];
    int wrp = threadIdx.x >> 5, ln = threadIdx.x & 31;
    if (ln == 0) { sa[wrp] = s; sb[wrp] = s2; }
    __syncthreads();
    if (threadIdx.x == 0) {
        float ts = 0.f, ts2 = 0.f;
        #pragma unroll
        for (int i = 0; i < 8; i++) { ts += sa[i]; ts2 += sb[i]; }
        const float invn = 1.f / (float)(BB * TT);
        float m = ts * invn;
        float var = ts2 * invn - m * m;
        g_mean[c] = m;
        g_rstd[c] = __fdiv_rn(1.0f, __fsqrt_rn(__fadd_rn(var, 1e-5f)));
    }
}

// ---------------- VQ ----------------
__global__ void cnorm_exact(const float* __restrict__ cb)
{
    int c = blockIdx.x * 256 + threadIdx.x;
    if (c == 0) g_loss = 0.f;
    if (c >= KCODES) return;
    float s = 0.f;
    #pragma unroll
    for (int d = 0; d < DDIM; d++) {
        float v = cb[c * DDIM + d];
        s = __fadd_rn(s, __fmul_rn(v, v));
    }
    g_cnorm[c] = s;
}

__global__ __launch_bounds__(128)
void vq_exact(const float* __restrict__ z, const float* __restrict__ cb,
              float* __restrict__ q, float* __restrict__ idx_out)
{
    __shared__ __align__(16) float cs[128 * DDIM];
    __shared__ float cn[128];
    __shared__ float red[4];

    const int tid = threadIdx.x;
    const int n = blockIdx.x * 128 + tid;
    const int b = n >> 12;
    const int t = n & (TT - 1);

    float zv[DDIM];
    #pragma unroll
    for (int d = 0; d < DDIM; d++) zv[d] = z[(size_t)(b * DDIM + d) * TT + t];

    float s1 = 0.f;
    #pragma unroll
    for (int d = 0; d < DDIM; d++) s1 = __fadd_rn(s1, __fmul_rn(zv[d], zv[d]));

    float best = 3.402823466e38f;
    int bidx = 0;

    for (int ch = 0; ch < KCODES / 128; ++ch) {
        __syncthreads();
        for (int i = tid; i < 128 * DDIM; i += 128)
            cs[i] = cb[ch * 128 * DDIM + i];
        cn[tid] = g_cnorm[ch * 128 + tid];
        __syncthreads();

        #pragma unroll 4
        for (int c = 0; c < 128; ++c) {
            const float4* cv = (const float4*)&cs[c * DDIM];
            float dot = 0.f;
            #pragma unroll
            for (int d4 = 0; d4 < DDIM / 4; d4++) {
                float4 v = cv[d4];
                dot = __fmaf_rn(zv[4 * d4 + 0], v.x, dot);
                dot = __fmaf_rn(zv[4 * d4 + 1], v.y, dot);
                dot = __fmaf_rn(zv[4 * d4 + 2], v.z, dot);
                dot = __fmaf_rn(zv[4 * d4 + 3], v.w, dot);
            }
            float a  = __fadd_rn(s1, cn[c]);
            float d2 = __fsub_rn(a, __fmul_rn(2.0f, dot));
            if (d2 < best) { best = d2; bidx = ch * 128 + c; }
        }
    }

    idx_out[n] = (float)bidx;

    float lsum = 0.f;
    #pragma unroll
    for (int d = 0; d < DDIM; d++) {
        float cv = cb[bidx * DDIM + d];
        float qst = __fadd_rn(zv[d], __fsub_rn(cv, zv[d]));
        q[(size_t)(b * DDIM + d) * TT + t] = qst;
        float df = cv - zv[d];
        lsum += df * df;
    }
    #pragma unroll
    for (int o = 16; o > 0; o >>= 1)
        lsum += __shfl_down_sync(0xffffffffu, lsum, o);
    if ((tid & 31) == 0) red[tid >> 5] = lsum;
    __syncthreads();
    if (tid == 0)
        atomicAdd(&g_loss, red[0] + red[1] + red[2] + red[3]);
}

__global__ void finalize_kernel(float* __restrict__ out)
{
    out[REC_ELEMS] = 1.25f * g_loss / (float)(BB * TT * DDIM);
}

// ---------------- launch ----------------
extern "C" void kernel_launch(void* const* d_in, const int* in_sizes, int n_in,
                              void* d_out, int out_size)
{
    const float* x      = (const float*)d_in[0];
    const float* enc_w1 = (const float*)d_in[1];
    const float* enc_b1 = (const float*)d_in[2];
    const float* bn1_g  = (const float*)d_in[3];
    const float* bn1_b  = (const float*)d_in[4];
    const float* enc_w2 = (const float*)d_in[5];
    const float* enc_b2 = (const float*)d_in[6];
    const float* bn2_g  = (const float*)d_in[7];
    const float* bn2_b  = (const float*)d_in[8];
    const float* enc_w3 = (const float*)d_in[9];
    const float* enc_b3 = (const float*)d_in[10];
    const float* cb     = (const float*)d_in[11];
    const float* dec_w1 = (const float*)d_in[12];
    const float* dec_b1 = (const float*)d_in[13];
    const float* dbn1_g = (const float*)d_in[14];
    const float* dbn1_b = (const float*)d_in[15];
    const float* dec_w2 = (const float*)d_in[16];
    const float* dec_b2 = (const float*)d_in[17];
    const float* dbn2_g = (const float*)d_in[18];
    const float* dbn2_b = (const float*)d_in[19];
    const float* dec_w3 = (const float*)d_in[20];
    const float* dec_b3 = (const float*)d_in[21];

    float* out = (float*)d_out;
    float* idx_out = out + REC_ELEMS + 1;

    float *buf1, *buf2, *zb, *qb;
    cudaGetSymbolAddress((void**)&buf1, g_buf1);
    cudaGetSymbolAddress((void**)&buf2, g_buf2);
    cudaGetSymbolAddress((void**)&zb,   g_z);
    cudaGetSymbolAddress((void**)&qb,   g_q);

    const dim3 blk(256);
    const int tg = TT / 256;   // 16

    // ---- encoder (bitwise-frozen arithmetic; BN fused into next conv's staging) ----
    conv_exact<3, false><<<dim3(tg, H1C / 64, BB), blk>>>(
        x, enc_w1, enc_b1, buf1, CIN, H1C, nullptr, nullptr);
    bnstats_warpchain<<<H1C, 512>>>(buf1, H1C);

    conv_exact<3, true><<<dim3(tg, H2C / 64, BB), blk>>>(
        buf1, enc_w2, enc_b2, buf2, H1C, H2C, bn1_g, bn1_b);
    bnstats_warpchain<<<H2C, 512>>>(buf2, H2C);

    conv_exact<1, true><<<dim3(tg, DDIM / 64, BB), blk>>>(
        buf2, enc_w3, enc_b3, zb, H2C, DDIM, bn2_g, bn2_b);

    // ---- VQ (bitwise d2) ----
    cnorm_exact<<<(KCODES + 255) / 256, 256>>>(cb);
    vq_exact<<<(BB * TT) / 128, 128>>>(zb, cb, qb, idx_out);

    // ---- decoder (1e-3 tolerance path) ----
    conv_fast<false><<<dim3(tg, H2C / 64, BB), blk>>>(
        qb, dec_w1, dec_b1, buf1, DDIM, H2C, nullptr, nullptr);
    bnstats_fast<<<H2C, 256>>>(buf1, H2C);

    conv_fast<true><<<dim3(tg, H1C / 64, BB), blk>>>(
        buf1, dec_w2, dec_b2, buf2, H2C, H1C, dbn1_g, dbn1_b);
    bnstats_fast<<<H1C, 256>>>(buf2, H1C);

    conv_fast<true><<<dim3(tg, 2, BB), blk>>>(
        buf2, dec_w3, dec_b3, out, H1C, CIN, dbn2_g, dbn2_b);

    finalize_kernel<<<1, 1>>>(out);
}